// round 3
// baseline (speedup 1.0000x reference)
#include <cuda_runtime.h>

#define EMB   1024
#define HEADS 16
#define HD    64
#define BATCH 4
#define SEQ   2048
#define NROWS (BATCH * SEQ)      // 8192
#define QKVW  (3 * EMB)          // 3072

// Scratch (allocation-free rule: __device__ globals)
__device__ float g_qkv[(size_t)NROWS * QKVW];   // 96 MB
__device__ float g_attn[(size_t)NROWS * EMB];   // 32 MB

// ---------------------------------------------------------------------------
// SGEMM: C[M,N] = A[M,K] @ B[K,N] + bias[N]   (row-major, M%128==0, N%128==0, K%8==0)
// 128x128 block tile, K-tile 8, 256 threads, 8x8 per thread, global->reg
// double buffering.
// ---------------------------------------------------------------------------
__global__ __launch_bounds__(256, 2)
void sgemm_bias_kernel(const float* __restrict__ A, const float* __restrict__ B,
                       const float* __restrict__ bias, float* __restrict__ C,
                       int M, int N, int K)
{
    __shared__ float As[8][128];
    __shared__ float Bs[8][128];

    const int tid  = threadIdx.x;
    const int tx   = tid & 15;          // column group (0..15)
    const int ty   = tid >> 4;          // row group    (0..15)
    const int row0 = blockIdx.y * 128;
    const int col0 = blockIdx.x * 128;

    // A tile loaders: 128 rows x 8 cols, 2 threads/row, float4 each
    const int a_r = tid >> 1;
    const int a_c = (tid & 1) << 2;
    // B tile loaders: 8 rows x 128 cols, 32 threads/row, float4 each
    const int b_r = tid >> 5;
    const int b_c = (tid & 31) << 2;

    const float* Ap = A + (size_t)(row0 + a_r) * K + a_c;
    const float* Bp = B + (size_t)b_r * N + (col0 + b_c);

    float acc[8][8];
    #pragma unroll
    for (int i = 0; i < 8; i++)
        #pragma unroll
        for (int j = 0; j < 8; j++)
            acc[i][j] = 0.f;

    float4 av = *(const float4*)Ap;
    float4 bv = *(const float4*)Bp;

    for (int k0 = 0; k0 < K; k0 += 8) {
        // store current tile to smem (A transposed so reads are [k][row])
        As[a_c + 0][a_r] = av.x;
        As[a_c + 1][a_r] = av.y;
        As[a_c + 2][a_r] = av.z;
        As[a_c + 3][a_r] = av.w;
        *(float4*)&Bs[b_r][b_c] = bv;
        __syncthreads();

        // prefetch next tile into registers while computing
        if (k0 + 8 < K) {
            Ap += 8;
            Bp += (size_t)8 * N;
            av = *(const float4*)Ap;
            bv = *(const float4*)Bp;
        }

        #pragma unroll
        for (int k = 0; k < 8; k++) {
            float4 a0 = *(const float4*)&As[k][ty * 8];
            float4 a1 = *(const float4*)&As[k][ty * 8 + 4];
            float4 b0 = *(const float4*)&Bs[k][tx * 8];
            float4 b1 = *(const float4*)&Bs[k][tx * 8 + 4];
            float af[8] = {a0.x, a0.y, a0.z, a0.w, a1.x, a1.y, a1.z, a1.w};
            float bf[8] = {b0.x, b0.y, b0.z, b0.w, b1.x, b1.y, b1.z, b1.w};
            #pragma unroll
            for (int i = 0; i < 8; i++)
                #pragma unroll
                for (int j = 0; j < 8; j++)
                    acc[i][j] += af[i] * bf[j];
        }
        __syncthreads();
    }

    float4 bb0 = *(const float4*)&bias[col0 + tx * 8];
    float4 bb1 = *(const float4*)&bias[col0 + tx * 8 + 4];
    #pragma unroll
    for (int i = 0; i < 8; i++) {
        float* Cp = C + (size_t)(row0 + ty * 8 + i) * N + col0 + tx * 8;
        float4 o0 = make_float4(acc[i][0] + bb0.x, acc[i][1] + bb0.y,
                                acc[i][2] + bb0.z, acc[i][3] + bb0.w);
        float4 o1 = make_float4(acc[i][4] + bb1.x, acc[i][5] + bb1.y,
                                acc[i][6] + bb1.z, acc[i][7] + bb1.w);
        *(float4*)Cp       = o0;
        *(float4*)(Cp + 4) = o1;
    }
}

// ---------------------------------------------------------------------------
// Flash attention (fp32, online softmax).
// One block per (b, h, q-tile of 64 rows). 128 threads.
// Thread (rt, ct): rt = tid/8 owns q rows rt*4..+4; ct = tid%8 owns 8 cols
// (k cols for scores, d cols for output). smem operands stored so every
// inner-loop LDS is a conflict-free float4:
//   Qt  [d][q]   (transposed, pre-scaled by 1/sqrt(D))
//   KPt [d][k]   (K transposed) -- reused as P^T [k][q] after softmax
//   Vs  [k][d]   (natural)
// Static smem = 3 * 64*64*4 = 49152 B (48 KB) -> 4 blocks/SM.
// ---------------------------------------------------------------------------
__global__ __launch_bounds__(128, 4)
void flash_attn_kernel(const float* __restrict__ qkv, float* __restrict__ attn)
{
    __shared__ float Qt[64][64];
    __shared__ float KPt[64][64];
    __shared__ float Vs[64][64];

    const int tid = threadIdx.x;
    const int qt  = blockIdx.x;          // q tile (0..31)
    const int b   = blockIdx.y >> 4;
    const int h   = blockIdx.y & 15;

    const float* Qg = qkv + (size_t)(b * SEQ + qt * 64) * QKVW + h * HD;
    const float* Kg = qkv + (size_t)(b * SEQ) * QKVW + EMB     + h * HD;
    const float* Vg = qkv + (size_t)(b * SEQ) * QKVW + 2 * EMB + h * HD;

    // Load Q tile transposed & pre-scaled by 1/sqrt(64)
    {
        const int r  = tid >> 1;
        const int c0 = (tid & 1) * 32;
        const float* p = Qg + (size_t)r * QKVW + c0;
        #pragma unroll
        for (int v = 0; v < 8; v++) {
            float4 x = *(const float4*)(p + v * 4);
            int c = c0 + v * 4;
            Qt[c + 0][r] = x.x * 0.125f;
            Qt[c + 1][r] = x.y * 0.125f;
            Qt[c + 2][r] = x.z * 0.125f;
            Qt[c + 3][r] = x.w * 0.125f;
        }
    }

    const int rt = tid >> 3;   // 0..15
    const int ct = tid & 7;    // 0..7

    float m[4], l[4], o[4][8];
    #pragma unroll
    for (int i = 0; i < 4; i++) {
        m[i] = -1e30f;
        l[i] = 0.f;
        #pragma unroll
        for (int j = 0; j < 8; j++) o[i][j] = 0.f;
    }

    for (int kt = 0; kt < SEQ / 64; kt++) {
        __syncthreads();   // previous iteration's smem reads complete

        // Load K tile transposed into KPt
        {
            const int r  = tid >> 1;
            const int c0 = (tid & 1) * 32;
            const float* pk = Kg + (size_t)(kt * 64 + r) * QKVW + c0;
            #pragma unroll
            for (int v = 0; v < 8; v++) {
                float4 x = *(const float4*)(pk + v * 4);
                int c = c0 + v * 4;
                KPt[c + 0][r] = x.x;
                KPt[c + 1][r] = x.y;
                KPt[c + 2][r] = x.z;
                KPt[c + 3][r] = x.w;
            }
        }
        // Load V tile natural (linearized mapping -> conflict-free float4 stores)
        #pragma unroll
        for (int v = 0; v < 8; v++) {
            int f = v * 128 + tid;
            int r = f >> 4;
            int c = (f & 15) * 4;
            float4 y = *(const float4*)(Vg + (size_t)(kt * 64 + r) * QKVW + c);
            *(float4*)&Vs[r][c] = y;
        }
        __syncthreads();

        // Scores: s[i][j] = (Q_row . K_col) / 8   (scale folded into Qt)
        float s[4][8];
        #pragma unroll
        for (int i = 0; i < 4; i++)
            #pragma unroll
            for (int j = 0; j < 8; j++) s[i][j] = 0.f;

        #pragma unroll 4
        for (int d = 0; d < 64; d++) {
            float4 a  = *(const float4*)&Qt[d][rt * 4];
            float4 b0 = *(const float4*)&KPt[d][ct * 8];
            float4 b1 = *(const float4*)&KPt[d][ct * 8 + 4];
            float af[4] = {a.x, a.y, a.z, a.w};
            float bf[8] = {b0.x, b0.y, b0.z, b0.w, b1.x, b1.y, b1.z, b1.w};
            #pragma unroll
            for (int i = 0; i < 4; i++)
                #pragma unroll
                for (int j = 0; j < 8; j++)
                    s[i][j] += af[i] * bf[j];
        }

        // Online softmax. Each q row is owned by 8 consecutive lanes (same rt),
        // aligned within a warp -> shfl_xor(1,2,4) reduces across the row.
        #pragma unroll
        for (int i = 0; i < 4; i++) {
            float mx = s[i][0];
            #pragma unroll
            for (int j = 1; j < 8; j++) mx = fmaxf(mx, s[i][j]);
            mx = fmaxf(mx, __shfl_xor_sync(0xffffffffu, mx, 1));
            mx = fmaxf(mx, __shfl_xor_sync(0xffffffffu, mx, 2));
            mx = fmaxf(mx, __shfl_xor_sync(0xffffffffu, mx, 4));
            float mn    = fmaxf(m[i], mx);
            float alpha = __expf(m[i] - mn);
            m[i] = mn;
            float sum = 0.f;
            #pragma unroll
            for (int j = 0; j < 8; j++) {
                s[i][j] = __expf(s[i][j] - mn);
                sum += s[i][j];
            }
            sum += __shfl_xor_sync(0xffffffffu, sum, 1);
            sum += __shfl_xor_sync(0xffffffffu, sum, 2);
            sum += __shfl_xor_sync(0xffffffffu, sum, 4);
            l[i] = l[i] * alpha + sum;
            #pragma unroll
            for (int j = 0; j < 8; j++) o[i][j] *= alpha;
        }

        __syncthreads();   // all K reads done; KPt can be reused as P^T
        #pragma unroll
        for (int j = 0; j < 8; j++)
            *(float4*)&KPt[ct * 8 + j][rt * 4] =
                make_float4(s[0][j], s[1][j], s[2][j], s[3][j]);
        __syncthreads();

        // o += P @ V : o[i][j] += sum_k P^T[k][q_i] * V[k][d_j]
        #pragma unroll 4
        for (int kk = 0; kk < 64; kk++) {
            float4 a  = *(const float4*)&KPt[kk][rt * 4];
            float4 b0 = *(const float4*)&Vs[kk][ct * 8];
            float4 b1 = *(const float4*)&Vs[kk][ct * 8 + 4];
            float af[4] = {a.x, a.y, a.z, a.w};
            float bf[8] = {b0.x, b0.y, b0.z, b0.w, b1.x, b1.y, b1.z, b1.w};
            #pragma unroll
            for (int i = 0; i < 4; i++)
                #pragma unroll
                for (int j = 0; j < 8; j++)
                    o[i][j] += af[i] * bf[j];
        }
    }

    // Epilogue: normalize and write [B*S, E] with head offset
    #pragma unroll
    for (int i = 0; i < 4; i++) {
        float inv = 1.f / l[i];
        float* p = attn + (size_t)(b * SEQ + qt * 64 + rt * 4 + i) * EMB
                        + h * HD + ct * 8;
        *(float4*)p       = make_float4(o[i][0] * inv, o[i][1] * inv,
                                        o[i][2] * inv, o[i][3] * inv);
        *(float4*)(p + 4) = make_float4(o[i][4] * inv, o[i][5] * inv,
                                        o[i][6] * inv, o[i][7] * inv);
    }
}

// ---------------------------------------------------------------------------
extern "C" void kernel_launch(void* const* d_in, const int* in_sizes, int n_in,
                              void* d_out, int out_size)
{
    (void)in_sizes; (void)n_in; (void)out_size;
    const float* x     = (const float*)d_in[0];   // [B,S,E]
    const float* w_qkv = (const float*)d_in[1];   // [E,3E]
    const float* b_qkv = (const float*)d_in[2];   // [3E]
    const float* w_out = (const float*)d_in[3];   // [E,E]
    const float* b_out = (const float*)d_in[4];   // [E]
    float* out = (float*)d_out;                   // [B,S,E]

    float* qkv  = nullptr;
    float* attn = nullptr;
    cudaGetSymbolAddress((void**)&qkv,  g_qkv);
    cudaGetSymbolAddress((void**)&attn, g_attn);

    // 1) QKV projection: [8192,1024] @ [1024,3072] + b
    sgemm_bias_kernel<<<dim3(QKVW / 128, NROWS / 128), 256>>>(
        x, w_qkv, b_qkv, qkv, NROWS, QKVW, EMB);

    // 2) Attention per (b,h,q-tile)
    flash_attn_kernel<<<dim3(SEQ / 64, BATCH * HEADS), 128>>>(qkv, attn);

    // 3) Output projection: [8192,1024] @ [1024,1024] + b
    sgemm_bias_kernel<<<dim3(EMB / 128, NROWS / 128), 256>>>(
        attn, w_out, b_out, out, NROWS, EMB, EMB);
}

// round 4
// speedup vs baseline: 1.0036x; 1.0036x over previous
#include <cuda_runtime.h>

#define EMB   1024
#define HEADS 16
#define HD    64
#define BATCH 4
#define SEQ   2048
#define NROWS (BATCH * SEQ)      // 8192
#define QKVW  (3 * EMB)          // 3072

// Scratch (allocation-free rule: __device__ globals)
__device__ float g_qkv[(size_t)NROWS * QKVW];   // 96 MB
__device__ float g_attn[(size_t)NROWS * EMB];   // 32 MB

// ---------------------------------------------------------------------------
// f32x2 packed-FMA helpers (sm_103a FFMA2: 2 fp32 FMAs per instruction)
// ---------------------------------------------------------------------------
typedef unsigned long long u64;

__device__ __forceinline__ u64 pk2(float lo, float hi) {
    u64 r;
    asm("mov.b64 %0, {%1, %2};" : "=l"(r) : "f"(lo), "f"(hi));
    return r;
}
__device__ __forceinline__ u64 dup2(float x) { return pk2(x, x); }

__device__ __forceinline__ void fma2(u64& d, u64 a, u64 b) {
    asm("fma.rn.f32x2 %0, %1, %2, %0;" : "+l"(d) : "l"(a), "l"(b));
}
__device__ __forceinline__ void mul2(u64& d, u64 a) {
    asm("mul.rn.f32x2 %0, %0, %1;" : "+l"(d) : "l"(a));
}
__device__ __forceinline__ float2 unpk(u64 v) {
    float2 f;
    asm("mov.b64 {%0, %1}, %2;" : "=f"(f.x), "=f"(f.y) : "l"(v));
    return f;
}

// ---------------------------------------------------------------------------
// SGEMM: C[M,N] = A[M,K] @ B[K,N] + bias[N]   (row-major, M%128==0, N%128==0, K%8==0)
// 128x128 block tile, K-tile 8, 256 threads, 8x8 per thread via FFMA2.
// ---------------------------------------------------------------------------
__global__ __launch_bounds__(256, 2)
void sgemm_bias_kernel(const float* __restrict__ A, const float* __restrict__ B,
                       const float* __restrict__ bias, float* __restrict__ C,
                       int M, int N, int K)
{
    __shared__ float As[8][128];
    __shared__ float Bs[8][128];

    const int tid  = threadIdx.x;
    const int tx   = tid & 15;          // column group (0..15)
    const int ty   = tid >> 4;          // row group    (0..15)
    const int row0 = blockIdx.y * 128;
    const int col0 = blockIdx.x * 128;

    // A tile loaders: 128 rows x 8 cols, 2 threads/row, float4 each
    const int a_r = tid >> 1;
    const int a_c = (tid & 1) << 2;
    // B tile loaders: 8 rows x 128 cols, 32 threads/row, float4 each
    const int b_r = tid >> 5;
    const int b_c = (tid & 31) << 2;

    const float* Ap = A + (size_t)(row0 + a_r) * K + a_c;
    const float* Bp = B + (size_t)b_r * N + (col0 + b_c);

    // acc[i][j] pairs packed along j: accp[i][j2] = (acc[i][2*j2], acc[i][2*j2+1])
    u64 accp[8][4];
    #pragma unroll
    for (int i = 0; i < 8; i++)
        #pragma unroll
        for (int j = 0; j < 4; j++)
            accp[i][j] = 0ull;          // bitwise (+0.0f, +0.0f)

    float4 av = *(const float4*)Ap;
    float4 bv = *(const float4*)Bp;

    for (int k0 = 0; k0 < K; k0 += 8) {
        // store current tile to smem (A transposed so reads are [k][row])
        As[a_c + 0][a_r] = av.x;
        As[a_c + 1][a_r] = av.y;
        As[a_c + 2][a_r] = av.z;
        As[a_c + 3][a_r] = av.w;
        *(float4*)&Bs[b_r][b_c] = bv;
        __syncthreads();

        // prefetch next tile into registers while computing
        if (k0 + 8 < K) {
            Ap += 8;
            Bp += (size_t)8 * N;
            av = *(const float4*)Ap;
            bv = *(const float4*)Bp;
        }

        #pragma unroll
        for (int k = 0; k < 8; k++) {
            float4 a0 = *(const float4*)&As[k][ty * 8];
            float4 a1 = *(const float4*)&As[k][ty * 8 + 4];
            // B pairs load naturally as 64-bit lanes (32B-aligned base)
            ulonglong2 b01 = *(const ulonglong2*)&Bs[k][tx * 8];
            ulonglong2 b23 = *(const ulonglong2*)&Bs[k][tx * 8 + 4];
            u64 bp[4] = {b01.x, b01.y, b23.x, b23.y};
            float af[8] = {a0.x, a0.y, a0.z, a0.w, a1.x, a1.y, a1.z, a1.w};
            #pragma unroll
            for (int i = 0; i < 8; i++) {
                u64 ad = dup2(af[i]);
                #pragma unroll
                for (int j = 0; j < 4; j++)
                    fma2(accp[i][j], ad, bp[j]);
            }
        }
        __syncthreads();
    }

    float4 bb0 = *(const float4*)&bias[col0 + tx * 8];
    float4 bb1 = *(const float4*)&bias[col0 + tx * 8 + 4];
    float bb[8] = {bb0.x, bb0.y, bb0.z, bb0.w, bb1.x, bb1.y, bb1.z, bb1.w};
    #pragma unroll
    for (int i = 0; i < 8; i++) {
        float outv[8];
        #pragma unroll
        for (int j = 0; j < 4; j++) {
            float2 f = unpk(accp[i][j]);
            outv[2 * j]     = f.x + bb[2 * j];
            outv[2 * j + 1] = f.y + bb[2 * j + 1];
        }
        float* Cp = C + (size_t)(row0 + ty * 8 + i) * N + col0 + tx * 8;
        *(float4*)Cp       = make_float4(outv[0], outv[1], outv[2], outv[3]);
        *(float4*)(Cp + 4) = make_float4(outv[4], outv[5], outv[6], outv[7]);
    }
}

// ---------------------------------------------------------------------------
// Flash attention (fp32, online softmax), inner products via FFMA2.
// One block per (b, h, q-tile of 64 rows). 128 threads.
// Thread (rt, ct): rt = tid/8 owns q rows rt*4..+4; ct = tid%8 owns 8 cols.
//   Qt  [d][q]   (transposed, pre-scaled by 1/sqrt(D))
//   KPt [d][k]   (K transposed) -- reused as P^T [k][q] after softmax
//   Vs  [k][d]   (natural)
// Static smem = 48 KB -> 4 blocks/SM.
// ---------------------------------------------------------------------------
__global__ __launch_bounds__(128, 4)
void flash_attn_kernel(const float* __restrict__ qkv, float* __restrict__ attn)
{
    __shared__ float Qt[64][64];
    __shared__ float KPt[64][64];
    __shared__ float Vs[64][64];

    const int tid = threadIdx.x;
    const int qt  = blockIdx.x;          // q tile (0..31)
    const int b   = blockIdx.y >> 4;
    const int h   = blockIdx.y & 15;

    const float* Qg = qkv + (size_t)(b * SEQ + qt * 64) * QKVW + h * HD;
    const float* Kg = qkv + (size_t)(b * SEQ) * QKVW + EMB     + h * HD;
    const float* Vg = qkv + (size_t)(b * SEQ) * QKVW + 2 * EMB + h * HD;

    // Load Q tile transposed & pre-scaled by 1/sqrt(64)
    {
        const int r  = tid >> 1;
        const int c0 = (tid & 1) * 32;
        const float* p = Qg + (size_t)r * QKVW + c0;
        #pragma unroll
        for (int v = 0; v < 8; v++) {
            float4 x = *(const float4*)(p + v * 4);
            int c = c0 + v * 4;
            Qt[c + 0][r] = x.x * 0.125f;
            Qt[c + 1][r] = x.y * 0.125f;
            Qt[c + 2][r] = x.z * 0.125f;
            Qt[c + 3][r] = x.w * 0.125f;
        }
    }

    const int rt = tid >> 3;   // 0..15
    const int ct = tid & 7;    // 0..7

    float m[4], l[4];
    u64 op[4][4];              // o[i][j] packed along j
    #pragma unroll
    for (int i = 0; i < 4; i++) {
        m[i] = -1e30f;
        l[i] = 0.f;
        #pragma unroll
        for (int j = 0; j < 4; j++) op[i][j] = 0ull;
    }

    for (int kt = 0; kt < SEQ / 64; kt++) {
        __syncthreads();   // previous iteration's smem reads complete

        // Load K tile transposed into KPt
        {
            const int r  = tid >> 1;
            const int c0 = (tid & 1) * 32;
            const float* pk = Kg + (size_t)(kt * 64 + r) * QKVW + c0;
            #pragma unroll
            for (int v = 0; v < 8; v++) {
                float4 x = *(const float4*)(pk + v * 4);
                int c = c0 + v * 4;
                KPt[c + 0][r] = x.x;
                KPt[c + 1][r] = x.y;
                KPt[c + 2][r] = x.z;
                KPt[c + 3][r] = x.w;
            }
        }
        // Load V tile natural (linearized mapping -> conflict-free float4 stores)
        #pragma unroll
        for (int v = 0; v < 8; v++) {
            int f = v * 128 + tid;
            int r = f >> 4;
            int c = (f & 15) * 4;
            float4 y = *(const float4*)(Vg + (size_t)(kt * 64 + r) * QKVW + c);
            *(float4*)&Vs[r][c] = y;
        }
        __syncthreads();

        // Scores: s[i][j] = (Q_row . K_col) (scale folded into Qt), FFMA2 packed
        u64 sp[4][4];
        #pragma unroll
        for (int i = 0; i < 4; i++)
            #pragma unroll
            for (int j = 0; j < 4; j++) sp[i][j] = 0ull;

        #pragma unroll 4
        for (int d = 0; d < 64; d++) {
            float4 a = *(const float4*)&Qt[d][rt * 4];
            ulonglong2 b01 = *(const ulonglong2*)&KPt[d][ct * 8];
            ulonglong2 b23 = *(const ulonglong2*)&KPt[d][ct * 8 + 4];
            u64 bp[4] = {b01.x, b01.y, b23.x, b23.y};
            float af[4] = {a.x, a.y, a.z, a.w};
            #pragma unroll
            for (int i = 0; i < 4; i++) {
                u64 ad = dup2(af[i]);
                #pragma unroll
                for (int j = 0; j < 4; j++)
                    fma2(sp[i][j], ad, bp[j]);
            }
        }

        // Unpack scores for softmax
        float s[4][8];
        #pragma unroll
        for (int i = 0; i < 4; i++)
            #pragma unroll
            for (int j = 0; j < 4; j++) {
                float2 f = unpk(sp[i][j]);
                s[i][2 * j]     = f.x;
                s[i][2 * j + 1] = f.y;
            }

        // Online softmax. Each q row owned by 8 aligned lanes -> shfl_xor(1,2,4).
        #pragma unroll
        for (int i = 0; i < 4; i++) {
            float mx = s[i][0];
            #pragma unroll
            for (int j = 1; j < 8; j++) mx = fmaxf(mx, s[i][j]);
            mx = fmaxf(mx, __shfl_xor_sync(0xffffffffu, mx, 1));
            mx = fmaxf(mx, __shfl_xor_sync(0xffffffffu, mx, 2));
            mx = fmaxf(mx, __shfl_xor_sync(0xffffffffu, mx, 4));
            float mn    = fmaxf(m[i], mx);
            float alpha = __expf(m[i] - mn);
            m[i] = mn;
            float sum = 0.f;
            #pragma unroll
            for (int j = 0; j < 8; j++) {
                s[i][j] = __expf(s[i][j] - mn);
                sum += s[i][j];
            }
            sum += __shfl_xor_sync(0xffffffffu, sum, 1);
            sum += __shfl_xor_sync(0xffffffffu, sum, 2);
            sum += __shfl_xor_sync(0xffffffffu, sum, 4);
            l[i] = l[i] * alpha + sum;
            u64 ad = dup2(alpha);
            #pragma unroll
            for (int j = 0; j < 4; j++) mul2(op[i][j], ad);
        }

        __syncthreads();   // all K reads done; KPt can be reused as P^T
        #pragma unroll
        for (int j = 0; j < 8; j++)
            *(float4*)&KPt[ct * 8 + j][rt * 4] =
                make_float4(s[0][j], s[1][j], s[2][j], s[3][j]);
        __syncthreads();

        // o += P @ V : op[i][jp] += P^T[k][q_i] * V[k][d pairs], FFMA2 packed
        #pragma unroll 4
        for (int kk = 0; kk < 64; kk++) {
            float4 a = *(const float4*)&KPt[kk][rt * 4];
            ulonglong2 b01 = *(const ulonglong2*)&Vs[kk][ct * 8];
            ulonglong2 b23 = *(const ulonglong2*)&Vs[kk][ct * 8 + 4];
            u64 bp[4] = {b01.x, b01.y, b23.x, b23.y};
            float af[4] = {a.x, a.y, a.z, a.w};
            #pragma unroll
            for (int i = 0; i < 4; i++) {
                u64 ad = dup2(af[i]);
                #pragma unroll
                for (int j = 0; j < 4; j++)
                    fma2(op[i][j], ad, bp[j]);
            }
        }
    }

    // Epilogue: normalize and write [B*S, E] with head offset
    #pragma unroll
    for (int i = 0; i < 4; i++) {
        float inv = 1.f / l[i];
        float ov[8];
        #pragma unroll
        for (int j = 0; j < 4; j++) {
            float2 f = unpk(op[i][j]);
            ov[2 * j]     = f.x * inv;
            ov[2 * j + 1] = f.y * inv;
        }
        float* p = attn + (size_t)(b * SEQ + qt * 64 + rt * 4 + i) * EMB
                        + h * HD + ct * 8;
        *(float4*)p       = make_float4(ov[0], ov[1], ov[2], ov[3]);
        *(float4*)(p + 4) = make_float4(ov[4], ov[5], ov[6], ov[7]);
    }
}

// ---------------------------------------------------------------------------
extern "C" void kernel_launch(void* const* d_in, const int* in_sizes, int n_in,
                              void* d_out, int out_size)
{
    (void)in_sizes; (void)n_in; (void)out_size;
    const float* x     = (const float*)d_in[0];   // [B,S,E]
    const float* w_qkv = (const float*)d_in[1];   // [E,3E]
    const float* b_qkv = (const float*)d_in[2];   // [3E]
    const float* w_out = (const float*)d_in[3];   // [E,E]
    const float* b_out = (const float*)d_in[4];   // [E]
    float* out = (float*)d_out;                   // [B,S,E]

    float* qkv  = nullptr;
    float* attn = nullptr;
    cudaGetSymbolAddress((void**)&qkv,  g_qkv);
    cudaGetSymbolAddress((void**)&attn, g_attn);

    // 1) QKV projection: [8192,1024] @ [1024,3072] + b
    sgemm_bias_kernel<<<dim3(QKVW / 128, NROWS / 128), 256>>>(
        x, w_qkv, b_qkv, qkv, NROWS, QKVW, EMB);

    // 2) Attention per (b,h,q-tile)
    flash_attn_kernel<<<dim3(SEQ / 64, BATCH * HEADS), 128>>>(qkv, attn);

    // 3) Output projection: [8192,1024] @ [1024,1024] + b
    sgemm_bias_kernel<<<dim3(EMB / 128, NROWS / 128), 256>>>(
        attn, w_out, b_out, out, NROWS, EMB, EMB);
}

// round 6
// speedup vs baseline: 1.2804x; 1.2759x over previous
#include <cuda_runtime.h>
#include <cuda_bf16.h>
#include <cstdint>

#define EMB   1024
#define HEADS 16
#define HD    64
#define BATCH 4
#define SEQ   2048
#define NROWS (BATCH * SEQ)      // 8192
#define QKVW  (3 * EMB)          // 3072

// Scratch (allocation-free rule: __device__ globals)
__device__ float g_qkv[(size_t)NROWS * QKVW];   // 96 MB
__device__ float g_attn[(size_t)NROWS * EMB];   // 32 MB

// ===========================================================================
// Helpers
// ===========================================================================
__device__ __forceinline__ uint32_t smem_u32(const void* p) {
    uint32_t a;
    asm("{ .reg .u64 t; cvta.to.shared.u64 t, %1; cvt.u32.u64 %0, t; }"
        : "=r"(a) : "l"(p));
    return a;
}

// Split a float2 into packed bf16x2: hi = truncated top-16 bits (exact
// residual), lo = rn-bf16 of residual. Low 16 bits = first element.
__device__ __forceinline__ void split_pair(float2 v, uint32_t& hi, uint32_t& lo) {
    uint32_t ax = __float_as_uint(v.x), bx = __float_as_uint(v.y);
    hi = __byte_perm(ax, bx, 0x7632);
    float lx = v.x - __uint_as_float(ax & 0xFFFF0000u);
    float ly = v.y - __uint_as_float(bx & 0xFFFF0000u);
    asm("cvt.rn.bf16x2.f32 %0, %1, %2;" : "=r"(lo) : "f"(ly), "f"(lx));
}

__device__ __forceinline__ void ldsm_x4(uint32_t* r, uint32_t addr) {
    asm volatile("ldmatrix.sync.aligned.m8n8.x4.shared.b16 {%0,%1,%2,%3}, [%4];"
                 : "=r"(r[0]), "=r"(r[1]), "=r"(r[2]), "=r"(r[3]) : "r"(addr));
}
__device__ __forceinline__ void ldsm_x4_t(uint32_t* r, uint32_t addr) {
    asm volatile("ldmatrix.sync.aligned.m8n8.x4.trans.shared.b16 {%0,%1,%2,%3}, [%4];"
                 : "=r"(r[0]), "=r"(r[1]), "=r"(r[2]), "=r"(r[3]) : "r"(addr));
}
__device__ __forceinline__ void mma_bf16(float* c, const uint32_t* a,
                                         const uint32_t* b) {
    asm volatile(
        "mma.sync.aligned.m16n8k16.row.col.f32.bf16.bf16.f32 "
        "{%0,%1,%2,%3}, {%4,%5,%6,%7}, {%8,%9}, {%0,%1,%2,%3};"
        : "+f"(c[0]), "+f"(c[1]), "+f"(c[2]), "+f"(c[3])
        : "r"(a[0]), "r"(a[1]), "r"(a[2]), "r"(a[3]), "r"(b[0]), "r"(b[1]));
}

// ===========================================================================
// Tensor-core GEMM (bf16x3 split, mma.sync): C[M,N] = A[M,K] @ B[K,N] + bias
// 128x128 block tile, K-chunk 16, 256 threads = 8 warps (4m x 2n),
// warp tile 32x64 (2 m16-tiles x 8 n8-tiles).
// ===========================================================================
#define AS_K 24     // padded k-extent of A smem rows (48 B, ldmatrix-conflict-free)
#define BS_N 136    // padded n-extent of B smem rows (272 B, ldmatrix-conflict-free)

__global__ __launch_bounds__(256)
void gemm_tc_kernel(const float* __restrict__ A, const float* __restrict__ B,
                    const float* __restrict__ bias, float* __restrict__ C,
                    int N, int K)
{
    __shared__ __align__(16) uint16_t As_hi[128][AS_K];
    __shared__ __align__(16) uint16_t As_lo[128][AS_K];
    __shared__ __align__(16) uint16_t Bs_hi[16][BS_N];
    __shared__ __align__(16) uint16_t Bs_lo[16][BS_N];

    const int tid  = threadIdx.x;
    const int lane = tid & 31;
    const int wid  = tid >> 5;
    const int wm   = wid & 3;           // warp m group (0..3) -> 32 rows
    const int wn   = wid >> 2;          // warp n group (0..1) -> 64 cols
    const int row0 = blockIdx.y * 128;
    const int col0 = blockIdx.x * 128;

    // ---- loader mappings ----
    const int m_a = tid >> 1;           // A: row (0..127)
    const int k_a = (tid & 1) * 8;      // A: k offset (0/8)
    const int k_b = tid >> 4;           // B: k row (0..15)
    const int n_b = (tid & 15) * 8;     // B: n offset (0..120)

    const float* Ap = A + (size_t)(row0 + m_a) * K + k_a;
    const float* Bp = B + (size_t)k_b * N + col0 + n_b;

    // ---- per-lane ldmatrix addresses (constant across K chunks) ----
    const int g  = lane >> 3;
    const int rr = lane & 7;
    uint32_t a_hi_ad[2], a_lo_ad[2];
    #pragma unroll
    for (int mt = 0; mt < 2; mt++) {
        int m_loc = wm * 32 + mt * 16 + (g & 1) * 8 + rr;
        int k_loc = (g >> 1) * 8;
        uint32_t off = (uint32_t)(m_loc * AS_K + k_loc) * 2u;
        a_hi_ad[mt] = smem_u32(As_hi) + off;
        a_lo_ad[mt] = smem_u32(As_lo) + off;
    }
    uint32_t b_hi_ad[4], b_lo_ad[4];
    #pragma unroll
    for (int np = 0; np < 4; np++) {
        int k_loc = (g & 1) * 8 + rr;
        int n_loc = wn * 64 + np * 16 + (g >> 1) * 8;
        uint32_t off = (uint32_t)(k_loc * BS_N + n_loc) * 2u;
        b_hi_ad[np] = smem_u32(Bs_hi) + off;
        b_lo_ad[np] = smem_u32(Bs_lo) + off;
    }

    float acc[2][8][4];
    #pragma unroll
    for (int i = 0; i < 2; i++)
        #pragma unroll
        for (int j = 0; j < 8; j++)
            #pragma unroll
            for (int r = 0; r < 4; r++)
                acc[i][j][r] = 0.f;

    float4 av0 = *(const float4*)Ap;
    float4 av1 = *(const float4*)(Ap + 4);
    float4 bv0 = *(const float4*)Bp;
    float4 bv1 = *(const float4*)(Bp + 4);

    for (int k0 = 0; k0 < K; k0 += 16) {
        // ---- convert + store current chunk ----
        {
            uint32_t h, l;
            split_pair(make_float2(av0.x, av0.y), h, l);
            *(uint32_t*)&As_hi[m_a][k_a + 0] = h;  *(uint32_t*)&As_lo[m_a][k_a + 0] = l;
            split_pair(make_float2(av0.z, av0.w), h, l);
            *(uint32_t*)&As_hi[m_a][k_a + 2] = h;  *(uint32_t*)&As_lo[m_a][k_a + 2] = l;
            split_pair(make_float2(av1.x, av1.y), h, l);
            *(uint32_t*)&As_hi[m_a][k_a + 4] = h;  *(uint32_t*)&As_lo[m_a][k_a + 4] = l;
            split_pair(make_float2(av1.z, av1.w), h, l);
            *(uint32_t*)&As_hi[m_a][k_a + 6] = h;  *(uint32_t*)&As_lo[m_a][k_a + 6] = l;

            split_pair(make_float2(bv0.x, bv0.y), h, l);
            *(uint32_t*)&Bs_hi[k_b][n_b + 0] = h;  *(uint32_t*)&Bs_lo[k_b][n_b + 0] = l;
            split_pair(make_float2(bv0.z, bv0.w), h, l);
            *(uint32_t*)&Bs_hi[k_b][n_b + 2] = h;  *(uint32_t*)&Bs_lo[k_b][n_b + 2] = l;
            split_pair(make_float2(bv1.x, bv1.y), h, l);
            *(uint32_t*)&Bs_hi[k_b][n_b + 4] = h;  *(uint32_t*)&Bs_lo[k_b][n_b + 4] = l;
            split_pair(make_float2(bv1.z, bv1.w), h, l);
            *(uint32_t*)&Bs_hi[k_b][n_b + 6] = h;  *(uint32_t*)&Bs_lo[k_b][n_b + 6] = l;
        }
        __syncthreads();

        // ---- prefetch next chunk ----
        if (k0 + 16 < K) {
            av0 = *(const float4*)(Ap + k0 + 16);
            av1 = *(const float4*)(Ap + k0 + 20);
            bv0 = *(const float4*)(Bp + (size_t)(k0 + 16) * N);
            bv1 = *(const float4*)(Bp + (size_t)(k0 + 16) * N + 4);
        }

        // ---- compute: 3-term split MMA ----
        uint32_t ahi[2][4], alo[2][4];
        ldsm_x4(ahi[0], a_hi_ad[0]);
        ldsm_x4(ahi[1], a_hi_ad[1]);
        ldsm_x4(alo[0], a_lo_ad[0]);
        ldsm_x4(alo[1], a_lo_ad[1]);

        #pragma unroll
        for (int np = 0; np < 4; np++) {
            uint32_t bh[4], bl[4];
            ldsm_x4_t(bh, b_hi_ad[np]);
            ldsm_x4_t(bl, b_lo_ad[np]);
            #pragma unroll
            for (int mt = 0; mt < 2; mt++) {
                mma_bf16(acc[mt][2 * np + 0], ahi[mt], bh);       // Ahi*Bhi (n0-7)
                mma_bf16(acc[mt][2 * np + 0], ahi[mt], bl);       // Ahi*Blo
                mma_bf16(acc[mt][2 * np + 0], alo[mt], bh);       // Alo*Bhi
                mma_bf16(acc[mt][2 * np + 1], ahi[mt], bh + 2);   // n8-15
                mma_bf16(acc[mt][2 * np + 1], ahi[mt], bl + 2);
                mma_bf16(acc[mt][2 * np + 1], alo[mt], bh + 2);
            }
        }
        __syncthreads();
    }

    // ---- epilogue ----
    const int ml = lane >> 2;           // 0..7
    const int nl = 2 * (lane & 3);      // 0,2,4,6
    #pragma unroll
    for (int mt = 0; mt < 2; mt++) {
        #pragma unroll
        for (int nt = 0; nt < 8; nt++) {
            int m = row0 + wm * 32 + mt * 16 + ml;
            int n = col0 + wn * 64 + nt * 8 + nl;
            float2 bv = *(const float2*)&bias[n];
            float* c = acc[mt][nt];
            *(float2*)(C + (size_t)m * N + n) =
                make_float2(c[0] + bv.x, c[1] + bv.y);
            *(float2*)(C + (size_t)(m + 8) * N + n) =
                make_float2(c[2] + bv.x, c[3] + bv.y);
        }
    }
}

// ===========================================================================
// Flash attention (fp32, online softmax) — unchanged from best passing round.
// ===========================================================================
typedef unsigned long long u64;
__device__ __forceinline__ u64 pk2(float lo, float hi) {
    u64 r; asm("mov.b64 %0, {%1, %2};" : "=l"(r) : "f"(lo), "f"(hi)); return r;
}
__device__ __forceinline__ u64 dup2(float x) { return pk2(x, x); }
__device__ __forceinline__ void fma2(u64& d, u64 a, u64 b) {
    asm("fma.rn.f32x2 %0, %1, %2, %0;" : "+l"(d) : "l"(a), "l"(b));
}
__device__ __forceinline__ void mul2(u64& d, u64 a) {
    asm("mul.rn.f32x2 %0, %0, %1;" : "+l"(d) : "l"(a));
}
__device__ __forceinline__ float2 unpk(u64 v) {
    float2 f; asm("mov.b64 {%0, %1}, %2;" : "=f"(f.x), "=f"(f.y) : "l"(v)); return f;
}

__global__ __launch_bounds__(128, 4)
void flash_attn_kernel(const float* __restrict__ qkv, float* __restrict__ attn)
{
    __shared__ float Qt[64][64];
    __shared__ float KPt[64][64];
    __shared__ float Vs[64][64];

    const int tid = threadIdx.x;
    const int qt  = blockIdx.x;
    const int b   = blockIdx.y >> 4;
    const int h   = blockIdx.y & 15;

    const float* Qg = qkv + (size_t)(b * SEQ + qt * 64) * QKVW + h * HD;
    const float* Kg = qkv + (size_t)(b * SEQ) * QKVW + EMB     + h * HD;
    const float* Vg = qkv + (size_t)(b * SEQ) * QKVW + 2 * EMB + h * HD;

    {
        const int r  = tid >> 1;
        const int c0 = (tid & 1) * 32;
        const float* p = Qg + (size_t)r * QKVW + c0;
        #pragma unroll
        for (int v = 0; v < 8; v++) {
            float4 x = *(const float4*)(p + v * 4);
            int c = c0 + v * 4;
            Qt[c + 0][r] = x.x * 0.125f;
            Qt[c + 1][r] = x.y * 0.125f;
            Qt[c + 2][r] = x.z * 0.125f;
            Qt[c + 3][r] = x.w * 0.125f;
        }
    }

    const int rt = tid >> 3;
    const int ct = tid & 7;

    float m[4], l[4];
    u64 op[4][4];
    #pragma unroll
    for (int i = 0; i < 4; i++) {
        m[i] = -1e30f; l[i] = 0.f;
        #pragma unroll
        for (int j = 0; j < 4; j++) op[i][j] = 0ull;
    }

    for (int kt = 0; kt < SEQ / 64; kt++) {
        __syncthreads();
        {
            const int r  = tid >> 1;
            const int c0 = (tid & 1) * 32;
            const float* pk = Kg + (size_t)(kt * 64 + r) * QKVW + c0;
            #pragma unroll
            for (int v = 0; v < 8; v++) {
                float4 x = *(const float4*)(pk + v * 4);
                int c = c0 + v * 4;
                KPt[c + 0][r] = x.x;
                KPt[c + 1][r] = x.y;
                KPt[c + 2][r] = x.z;
                KPt[c + 3][r] = x.w;
            }
        }
        #pragma unroll
        for (int v = 0; v < 8; v++) {
            int f = v * 128 + tid;
            int r = f >> 4;
            int c = (f & 15) * 4;
            float4 y = *(const float4*)(Vg + (size_t)(kt * 64 + r) * QKVW + c);
            *(float4*)&Vs[r][c] = y;
        }
        __syncthreads();

        u64 sp[4][4];
        #pragma unroll
        for (int i = 0; i < 4; i++)
            #pragma unroll
            for (int j = 0; j < 4; j++) sp[i][j] = 0ull;

        #pragma unroll 4
        for (int d = 0; d < 64; d++) {
            float4 a = *(const float4*)&Qt[d][rt * 4];
            ulonglong2 b01 = *(const ulonglong2*)&KPt[d][ct * 8];
            ulonglong2 b23 = *(const ulonglong2*)&KPt[d][ct * 8 + 4];
            u64 bp[4] = {b01.x, b01.y, b23.x, b23.y};
            float af[4] = {a.x, a.y, a.z, a.w};
            #pragma unroll
            for (int i = 0; i < 4; i++) {
                u64 ad = dup2(af[i]);
                #pragma unroll
                for (int j = 0; j < 4; j++) fma2(sp[i][j], ad, bp[j]);
            }
        }

        float s[4][8];
        #pragma unroll
        for (int i = 0; i < 4; i++)
            #pragma unroll
            for (int j = 0; j < 4; j++) {
                float2 f = unpk(sp[i][j]);
                s[i][2 * j] = f.x; s[i][2 * j + 1] = f.y;
            }

        #pragma unroll
        for (int i = 0; i < 4; i++) {
            float mx = s[i][0];
            #pragma unroll
            for (int j = 1; j < 8; j++) mx = fmaxf(mx, s[i][j]);
            mx = fmaxf(mx, __shfl_xor_sync(0xffffffffu, mx, 1));
            mx = fmaxf(mx, __shfl_xor_sync(0xffffffffu, mx, 2));
            mx = fmaxf(mx, __shfl_xor_sync(0xffffffffu, mx, 4));
            float mn    = fmaxf(m[i], mx);
            float alpha = __expf(m[i] - mn);
            m[i] = mn;
            float sum = 0.f;
            #pragma unroll
            for (int j = 0; j < 8; j++) {
                s[i][j] = __expf(s[i][j] - mn);
                sum += s[i][j];
            }
            sum += __shfl_xor_sync(0xffffffffu, sum, 1);
            sum += __shfl_xor_sync(0xffffffffu, sum, 2);
            sum += __shfl_xor_sync(0xffffffffu, sum, 4);
            l[i] = l[i] * alpha + sum;
            u64 ad = dup2(alpha);
            #pragma unroll
            for (int j = 0; j < 4; j++) mul2(op[i][j], ad);
        }

        __syncthreads();
        #pragma unroll
        for (int j = 0; j < 8; j++)
            *(float4*)&KPt[ct * 8 + j][rt * 4] =
                make_float4(s[0][j], s[1][j], s[2][j], s[3][j]);
        __syncthreads();

        #pragma unroll 4
        for (int kk = 0; kk < 64; kk++) {
            float4 a = *(const float4*)&KPt[kk][rt * 4];
            ulonglong2 b01 = *(const ulonglong2*)&Vs[kk][ct * 8];
            ulonglong2 b23 = *(const ulonglong2*)&Vs[kk][ct * 8 + 4];
            u64 bp[4] = {b01.x, b01.y, b23.x, b23.y};
            float af[4] = {a.x, a.y, a.z, a.w};
            #pragma unroll
            for (int i = 0; i < 4; i++) {
                u64 ad = dup2(af[i]);
                #pragma unroll
                for (int j = 0; j < 4; j++) fma2(op[i][j], ad, bp[j]);
            }
        }
    }

    #pragma unroll
    for (int i = 0; i < 4; i++) {
        float inv = 1.f / l[i];
        float ov[8];
        #pragma unroll
        for (int j = 0; j < 4; j++) {
            float2 f = unpk(op[i][j]);
            ov[2 * j]     = f.x * inv;
            ov[2 * j + 1] = f.y * inv;
        }
        float* p = attn + (size_t)(b * SEQ + qt * 64 + rt * 4 + i) * EMB
                        + h * HD + ct * 8;
        *(float4*)p       = make_float4(ov[0], ov[1], ov[2], ov[3]);
        *(float4*)(p + 4) = make_float4(ov[4], ov[5], ov[6], ov[7]);
    }
}

// ---------------------------------------------------------------------------
extern "C" void kernel_launch(void* const* d_in, const int* in_sizes, int n_in,
                              void* d_out, int out_size)
{
    (void)in_sizes; (void)n_in; (void)out_size;
    const float* x     = (const float*)d_in[0];
    const float* w_qkv = (const float*)d_in[1];
    const float* b_qkv = (const float*)d_in[2];
    const float* w_out = (const float*)d_in[3];
    const float* b_out = (const float*)d_in[4];
    float* out = (float*)d_out;

    float* qkv  = nullptr;
    float* attn = nullptr;
    cudaGetSymbolAddress((void**)&qkv,  g_qkv);
    cudaGetSymbolAddress((void**)&attn, g_attn);

    // 1) QKV projection: [8192,1024] @ [1024,3072] + b  (bf16x3 mma.sync)
    gemm_tc_kernel<<<dim3(QKVW / 128, NROWS / 128), 256>>>(
        x, w_qkv, b_qkv, qkv, QKVW, EMB);

    // 2) Attention per (b,h,q-tile)  (fp32)
    flash_attn_kernel<<<dim3(SEQ / 64, BATCH * HEADS), 128>>>(qkv, attn);

    // 3) Output projection: [8192,1024] @ [1024,1024] + b  (bf16x3 mma.sync)
    gemm_tc_kernel<<<dim3(EMB / 128, NROWS / 128), 256>>>(
        attn, w_out, b_out, out, EMB, EMB);
}

// round 7
// speedup vs baseline: 2.8187x; 2.2014x over previous
#include <cuda_runtime.h>
#include <cuda_bf16.h>
#include <cstdint>

#define EMB   1024
#define HEADS 16
#define HD    64
#define BATCH 4
#define SEQ   2048
#define NROWS (BATCH * SEQ)      // 8192
#define QKVW  (3 * EMB)          // 3072

// Scratch (allocation-free rule: __device__ globals)
__device__ float g_qkv[(size_t)NROWS * QKVW];   // 96 MB
__device__ float g_attn[(size_t)NROWS * EMB];   // 32 MB

// ===========================================================================
// Helpers
// ===========================================================================
__device__ __forceinline__ uint32_t smem_u32(const void* p) {
    uint32_t a;
    asm("{ .reg .u64 t; cvta.to.shared.u64 t, %1; cvt.u32.u64 %0, t; }"
        : "=r"(a) : "l"(p));
    return a;
}

// Split a float2 into packed bf16x2: hi = truncated top-16 bits (exact
// residual), lo = rn-bf16 of residual. Low 16 bits = first element.
__device__ __forceinline__ void split_pair(float2 v, uint32_t& hi, uint32_t& lo) {
    uint32_t ax = __float_as_uint(v.x), bx = __float_as_uint(v.y);
    hi = __byte_perm(ax, bx, 0x7632);
    float lx = v.x - __uint_as_float(ax & 0xFFFF0000u);
    float ly = v.y - __uint_as_float(bx & 0xFFFF0000u);
    asm("cvt.rn.bf16x2.f32 %0, %1, %2;" : "=r"(lo) : "f"(ly), "f"(lx));
}

__device__ __forceinline__ void ldsm_x4(uint32_t* r, uint32_t addr) {
    asm volatile("ldmatrix.sync.aligned.m8n8.x4.shared.b16 {%0,%1,%2,%3}, [%4];"
                 : "=r"(r[0]), "=r"(r[1]), "=r"(r[2]), "=r"(r[3]) : "r"(addr));
}
__device__ __forceinline__ void ldsm_x4_t(uint32_t* r, uint32_t addr) {
    asm volatile("ldmatrix.sync.aligned.m8n8.x4.trans.shared.b16 {%0,%1,%2,%3}, [%4];"
                 : "=r"(r[0]), "=r"(r[1]), "=r"(r[2]), "=r"(r[3]) : "r"(addr));
}
__device__ __forceinline__ void mma_bf16(float* c, const uint32_t* a,
                                         const uint32_t* b) {
    asm volatile(
        "mma.sync.aligned.m16n8k16.row.col.f32.bf16.bf16.f32 "
        "{%0,%1,%2,%3}, {%4,%5,%6,%7}, {%8,%9}, {%0,%1,%2,%3};"
        : "+f"(c[0]), "+f"(c[1]), "+f"(c[2]), "+f"(c[3])
        : "r"(a[0]), "r"(a[1]), "r"(a[2]), "r"(a[3]), "r"(b[0]), "r"(b[1]));
}

// ===========================================================================
// Tensor-core GEMM (bf16x3 split, mma.sync): C[M,N] = A[M,K] @ B[K,N] + bias
// (unchanged from best passing round)
// ===========================================================================
#define AS_K 24
#define BS_N 136

__global__ __launch_bounds__(256)
void gemm_tc_kernel(const float* __restrict__ A, const float* __restrict__ B,
                    const float* __restrict__ bias, float* __restrict__ C,
                    int N, int K)
{
    __shared__ __align__(16) uint16_t As_hi[128][AS_K];
    __shared__ __align__(16) uint16_t As_lo[128][AS_K];
    __shared__ __align__(16) uint16_t Bs_hi[16][BS_N];
    __shared__ __align__(16) uint16_t Bs_lo[16][BS_N];

    const int tid  = threadIdx.x;
    const int lane = tid & 31;
    const int wid  = tid >> 5;
    const int wm   = wid & 3;
    const int wn   = wid >> 2;
    const int row0 = blockIdx.y * 128;
    const int col0 = blockIdx.x * 128;

    const int m_a = tid >> 1;
    const int k_a = (tid & 1) * 8;
    const int k_b = tid >> 4;
    const int n_b = (tid & 15) * 8;

    const float* Ap = A + (size_t)(row0 + m_a) * K + k_a;
    const float* Bp = B + (size_t)k_b * N + col0 + n_b;

    const int g  = lane >> 3;
    const int rr = lane & 7;
    uint32_t a_hi_ad[2], a_lo_ad[2];
    #pragma unroll
    for (int mt = 0; mt < 2; mt++) {
        int m_loc = wm * 32 + mt * 16 + (g & 1) * 8 + rr;
        int k_loc = (g >> 1) * 8;
        uint32_t off = (uint32_t)(m_loc * AS_K + k_loc) * 2u;
        a_hi_ad[mt] = smem_u32(As_hi) + off;
        a_lo_ad[mt] = smem_u32(As_lo) + off;
    }
    uint32_t b_hi_ad[4], b_lo_ad[4];
    #pragma unroll
    for (int np = 0; np < 4; np++) {
        int k_loc = (g & 1) * 8 + rr;
        int n_loc = wn * 64 + np * 16 + (g >> 1) * 8;
        uint32_t off = (uint32_t)(k_loc * BS_N + n_loc) * 2u;
        b_hi_ad[np] = smem_u32(Bs_hi) + off;
        b_lo_ad[np] = smem_u32(Bs_lo) + off;
    }

    float acc[2][8][4];
    #pragma unroll
    for (int i = 0; i < 2; i++)
        #pragma unroll
        for (int j = 0; j < 8; j++)
            #pragma unroll
            for (int r = 0; r < 4; r++)
                acc[i][j][r] = 0.f;

    float4 av0 = *(const float4*)Ap;
    float4 av1 = *(const float4*)(Ap + 4);
    float4 bv0 = *(const float4*)Bp;
    float4 bv1 = *(const float4*)(Bp + 4);

    for (int k0 = 0; k0 < K; k0 += 16) {
        {
            uint32_t h, l;
            split_pair(make_float2(av0.x, av0.y), h, l);
            *(uint32_t*)&As_hi[m_a][k_a + 0] = h;  *(uint32_t*)&As_lo[m_a][k_a + 0] = l;
            split_pair(make_float2(av0.z, av0.w), h, l);
            *(uint32_t*)&As_hi[m_a][k_a + 2] = h;  *(uint32_t*)&As_lo[m_a][k_a + 2] = l;
            split_pair(make_float2(av1.x, av1.y), h, l);
            *(uint32_t*)&As_hi[m_a][k_a + 4] = h;  *(uint32_t*)&As_lo[m_a][k_a + 4] = l;
            split_pair(make_float2(av1.z, av1.w), h, l);
            *(uint32_t*)&As_hi[m_a][k_a + 6] = h;  *(uint32_t*)&As_lo[m_a][k_a + 6] = l;

            split_pair(make_float2(bv0.x, bv0.y), h, l);
            *(uint32_t*)&Bs_hi[k_b][n_b + 0] = h;  *(uint32_t*)&Bs_lo[k_b][n_b + 0] = l;
            split_pair(make_float2(bv0.z, bv0.w), h, l);
            *(uint32_t*)&Bs_hi[k_b][n_b + 2] = h;  *(uint32_t*)&Bs_lo[k_b][n_b + 2] = l;
            split_pair(make_float2(bv1.x, bv1.y), h, l);
            *(uint32_t*)&Bs_hi[k_b][n_b + 4] = h;  *(uint32_t*)&Bs_lo[k_b][n_b + 4] = l;
            split_pair(make_float2(bv1.z, bv1.w), h, l);
            *(uint32_t*)&Bs_hi[k_b][n_b + 6] = h;  *(uint32_t*)&Bs_lo[k_b][n_b + 6] = l;
        }
        __syncthreads();

        if (k0 + 16 < K) {
            av0 = *(const float4*)(Ap + k0 + 16);
            av1 = *(const float4*)(Ap + k0 + 20);
            bv0 = *(const float4*)(Bp + (size_t)(k0 + 16) * N);
            bv1 = *(const float4*)(Bp + (size_t)(k0 + 16) * N + 4);
        }

        uint32_t ahi[2][4], alo[2][4];
        ldsm_x4(ahi[0], a_hi_ad[0]);
        ldsm_x4(ahi[1], a_hi_ad[1]);
        ldsm_x4(alo[0], a_lo_ad[0]);
        ldsm_x4(alo[1], a_lo_ad[1]);

        #pragma unroll
        for (int np = 0; np < 4; np++) {
            uint32_t bh[4], bl[4];
            ldsm_x4_t(bh, b_hi_ad[np]);
            ldsm_x4_t(bl, b_lo_ad[np]);
            #pragma unroll
            for (int mt = 0; mt < 2; mt++) {
                mma_bf16(acc[mt][2 * np + 0], ahi[mt], bh);
                mma_bf16(acc[mt][2 * np + 0], ahi[mt], bl);
                mma_bf16(acc[mt][2 * np + 0], alo[mt], bh);
                mma_bf16(acc[mt][2 * np + 1], ahi[mt], bh + 2);
                mma_bf16(acc[mt][2 * np + 1], ahi[mt], bl + 2);
                mma_bf16(acc[mt][2 * np + 1], alo[mt], bh + 2);
            }
        }
        __syncthreads();
    }

    const int ml = lane >> 2;
    const int nl = 2 * (lane & 3);
    #pragma unroll
    for (int mt = 0; mt < 2; mt++) {
        #pragma unroll
        for (int nt = 0; nt < 8; nt++) {
            int m = row0 + wm * 32 + mt * 16 + ml;
            int n = col0 + wn * 64 + nt * 8 + nl;
            float2 bv = *(const float2*)&bias[n];
            float* c = acc[mt][nt];
            *(float2*)(C + (size_t)m * N + n) =
                make_float2(c[0] + bv.x, c[1] + bv.y);
            *(float2*)(C + (size_t)(m + 8) * N + n) =
                make_float2(c[2] + bv.x, c[3] + bv.y);
        }
    }
}

// ===========================================================================
// Flash attention, mma.sync bf16x3 split.
// Block = 128 q-rows x one (b,h); 256 threads = 8 warps, warp owns m16.
// K-tile 64, 32 iterations. Q/K/V split hi/lo in smem, rows padded to 72
// elems (144 B = 9x16B -> conflict-free ldmatrix AND conflict-free uint4
// stores). P conversion is in-register (C-frag -> A-frag identity).
// ===========================================================================
#define FA_PAD  72
#define O_QHI   0
#define O_QLO   (O_QHI + 128 * FA_PAD * 2)   // 18432
#define O_KHI   (O_QLO + 128 * FA_PAD * 2)   // 36864
#define O_KLO   (O_KHI + 64 * FA_PAD * 2)    // 46080
#define O_VHI   (O_KLO + 64 * FA_PAD * 2)    // 55296
#define O_VLO   (O_VHI + 64 * FA_PAD * 2)    // 64512
#define FA_SMEM (O_VLO + 64 * FA_PAD * 2)    // 73728

__global__ __launch_bounds__(256)
void flash_attn_mma_kernel(const float* __restrict__ qkv,
                           float* __restrict__ attn)
{
    extern __shared__ char fsm[];
    const uint32_t sb = smem_u32(fsm);

    const int tid  = threadIdx.x;
    const int lane = tid & 31;
    const int wm   = tid >> 5;          // warp 0..7 -> q rows wm*16..+16
    const int qt   = blockIdx.x;        // 0..15
    const int b    = blockIdx.y >> 4;
    const int h    = blockIdx.y & 15;

    const float* Qg = qkv + (size_t)(b * SEQ + qt * 128) * QKVW + h * HD;
    const float* Kg = qkv + (size_t)(b * SEQ) * QKVW + EMB     + h * HD;
    const float* Vg = qkv + (size_t)(b * SEQ) * QKVW + 2 * EMB + h * HD;

    // ---- load Q tile (pre-scaled by 1/8), split into smem ----
    {
        const int r  = tid >> 1;            // 0..127
        const int c0 = (tid & 1) * 32;      // elem offset
        const float* p = Qg + (size_t)r * QKVW + c0;
        uint32_t qh[16], ql[16];
        #pragma unroll
        for (int v = 0; v < 16; v++) {
            float2 x = *(const float2*)(p + 2 * v);
            x.x *= 0.125f; x.y *= 0.125f;
            split_pair(x, qh[v], ql[v]);
        }
        uint32_t base = (uint32_t)(r * FA_PAD + c0) * 2u;
        #pragma unroll
        for (int s = 0; s < 4; s++) {
            *(uint4*)(fsm + O_QHI + base + 16 * s) =
                make_uint4(qh[4*s], qh[4*s+1], qh[4*s+2], qh[4*s+3]);
            *(uint4*)(fsm + O_QLO + base + 16 * s) =
                make_uint4(ql[4*s], ql[4*s+1], ql[4*s+2], ql[4*s+3]);
        }
    }
    __syncthreads();

    // ---- preload Q fragments (held in registers for all 32 iterations) ----
    const int g  = lane >> 3;
    const int rr = lane & 7;
    uint32_t qhi[4][4], qlo[4][4];
    {
        uint32_t moff = (uint32_t)((wm * 16 + (g & 1) * 8 + rr) * FA_PAD) * 2u;
        #pragma unroll
        for (int t = 0; t < 4; t++) {
            uint32_t koff = (uint32_t)((g >> 1) * 8 + 16 * t) * 2u;
            ldsm_x4(qhi[t], sb + O_QHI + moff + koff);
            ldsm_x4(qlo[t], sb + O_QLO + moff + koff);
        }
    }

    // per-lane constant parts of K (non-trans) / V (trans) frag addresses
    const uint32_t kbase = (uint32_t)(((g >> 1) * 8 + rr) * FA_PAD + (g & 1) * 8) * 2u;
    const uint32_t vbase = (uint32_t)(((g & 1) * 8 + rr) * FA_PAD + (g >> 1) * 8) * 2u;

    float m0 = -1e30f, m1 = -1e30f, l0 = 0.f, l1 = 0.f;
    float o[8][4];
    #pragma unroll
    for (int j = 0; j < 8; j++)
        #pragma unroll
        for (int r = 0; r < 4; r++) o[j][r] = 0.f;

    for (int kt = 0; kt < SEQ / 64; kt++) {
        // ---- global loads (high MLP), then split + uint4 stores ----
        const int r  = tid >> 2;            // 0..63
        const int c0 = (tid & 3) * 16;      // elem offset
        const float* kp = Kg + (size_t)(kt * 64 + r) * QKVW + c0;
        const float* vp = Vg + (size_t)(kt * 64 + r) * QKVW + c0;
        float2 kv[8], vv[8];
        #pragma unroll
        for (int v = 0; v < 8; v++) kv[v] = *(const float2*)(kp + 2 * v);
        #pragma unroll
        for (int v = 0; v < 8; v++) vv[v] = *(const float2*)(vp + 2 * v);

        __syncthreads();   // previous iteration's frag reads complete

        {
            uint32_t kh[8], kl[8], vh[8], vl[8];
            #pragma unroll
            for (int v = 0; v < 8; v++) {
                split_pair(kv[v], kh[v], kl[v]);
                split_pair(vv[v], vh[v], vl[v]);
            }
            uint32_t base = (uint32_t)(r * FA_PAD + c0) * 2u;
            #pragma unroll
            for (int s = 0; s < 2; s++) {
                *(uint4*)(fsm + O_KHI + base + 16 * s) =
                    make_uint4(kh[4*s], kh[4*s+1], kh[4*s+2], kh[4*s+3]);
                *(uint4*)(fsm + O_KLO + base + 16 * s) =
                    make_uint4(kl[4*s], kl[4*s+1], kl[4*s+2], kl[4*s+3]);
                *(uint4*)(fsm + O_VHI + base + 16 * s) =
                    make_uint4(vh[4*s], vh[4*s+1], vh[4*s+2], vh[4*s+3]);
                *(uint4*)(fsm + O_VLO + base + 16 * s) =
                    make_uint4(vl[4*s], vl[4*s+1], vl[4*s+2], vl[4*s+3]);
            }
        }
        __syncthreads();

        // ---- S = Q K^T (3-term split) : s[8][4] over 64 k-cols ----
        float s[8][4];
        #pragma unroll
        for (int j = 0; j < 8; j++)
            #pragma unroll
            for (int r4 = 0; r4 < 4; r4++) s[j][r4] = 0.f;

        #pragma unroll
        for (int nt = 0; nt < 4; nt++) {
            #pragma unroll
            for (int t = 0; t < 4; t++) {
                uint32_t off = kbase + (uint32_t)(nt * 16 * FA_PAD + 16 * t) * 2u;
                uint32_t kh[4], kl[4];
                ldsm_x4(kh, sb + O_KHI + off);
                ldsm_x4(kl, sb + O_KLO + off);
                mma_bf16(s[2*nt + 0], qhi[t], kh);
                mma_bf16(s[2*nt + 0], qhi[t], kl);
                mma_bf16(s[2*nt + 0], qlo[t], kh);
                mma_bf16(s[2*nt + 1], qhi[t], kh + 2);
                mma_bf16(s[2*nt + 1], qhi[t], kl + 2);
                mma_bf16(s[2*nt + 1], qlo[t], kh + 2);
            }
        }

        // ---- online softmax (rows r = lane>>2 and r+8) ----
        float mx0 = -1e30f, mx1 = -1e30f;
        #pragma unroll
        for (int j = 0; j < 8; j++) {
            mx0 = fmaxf(mx0, fmaxf(s[j][0], s[j][1]));
            mx1 = fmaxf(mx1, fmaxf(s[j][2], s[j][3]));
        }
        mx0 = fmaxf(mx0, __shfl_xor_sync(0xffffffffu, mx0, 1));
        mx0 = fmaxf(mx0, __shfl_xor_sync(0xffffffffu, mx0, 2));
        mx1 = fmaxf(mx1, __shfl_xor_sync(0xffffffffu, mx1, 1));
        mx1 = fmaxf(mx1, __shfl_xor_sync(0xffffffffu, mx1, 2));

        float mn0 = fmaxf(m0, mx0), mn1 = fmaxf(m1, mx1);
        float a0 = __expf(m0 - mn0), a1 = __expf(m1 - mn1);
        m0 = mn0; m1 = mn1;

        float sum0 = 0.f, sum1 = 0.f;
        #pragma unroll
        for (int j = 0; j < 8; j++) {
            s[j][0] = __expf(s[j][0] - mn0);
            s[j][1] = __expf(s[j][1] - mn0);
            s[j][2] = __expf(s[j][2] - mn1);
            s[j][3] = __expf(s[j][3] - mn1);
            sum0 += s[j][0] + s[j][1];
            sum1 += s[j][2] + s[j][3];
        }
        sum0 += __shfl_xor_sync(0xffffffffu, sum0, 1);
        sum0 += __shfl_xor_sync(0xffffffffu, sum0, 2);
        sum1 += __shfl_xor_sync(0xffffffffu, sum1, 1);
        sum1 += __shfl_xor_sync(0xffffffffu, sum1, 2);
        l0 = l0 * a0 + sum0;
        l1 = l1 * a1 + sum1;

        #pragma unroll
        for (int j = 0; j < 8; j++) {
            o[j][0] *= a0; o[j][1] *= a0;
            o[j][2] *= a1; o[j][3] *= a1;
        }

        // ---- o += P V (3-term split); P frags built in-register ----
        #pragma unroll
        for (int t = 0; t < 4; t++) {
            uint32_t phi[4], plo[4];
            split_pair(make_float2(s[2*t][0],   s[2*t][1]),   phi[0], plo[0]);
            split_pair(make_float2(s[2*t][2],   s[2*t][3]),   phi[1], plo[1]);
            split_pair(make_float2(s[2*t+1][0], s[2*t+1][1]), phi[2], plo[2]);
            split_pair(make_float2(s[2*t+1][2], s[2*t+1][3]), phi[3], plo[3]);
            #pragma unroll
            for (int nt = 0; nt < 4; nt++) {
                uint32_t off = vbase + (uint32_t)(t * 16 * FA_PAD + nt * 16) * 2u;
                uint32_t vh[4], vl[4];
                ldsm_x4_t(vh, sb + O_VHI + off);
                ldsm_x4_t(vl, sb + O_VLO + off);
                mma_bf16(o[2*nt + 0], phi, vh);
                mma_bf16(o[2*nt + 0], phi, vl);
                mma_bf16(o[2*nt + 0], plo, vh);
                mma_bf16(o[2*nt + 1], phi, vh + 2);
                mma_bf16(o[2*nt + 1], phi, vl + 2);
                mma_bf16(o[2*nt + 1], plo, vh + 2);
            }
        }
    }

    // ---- epilogue: normalize, write [B*S, E] with head offset ----
    float inv0 = 1.f / l0, inv1 = 1.f / l1;
    int row = b * SEQ + qt * 128 + wm * 16 + (lane >> 2);
    float* p0 = attn + (size_t)row * EMB + h * HD + 2 * (lane & 3);
    #pragma unroll
    for (int j = 0; j < 8; j++) {
        *(float2*)(p0 + 8 * j) = make_float2(o[j][0] * inv0, o[j][1] * inv0);
        *(float2*)(p0 + (size_t)8 * EMB + 8 * j) =
            make_float2(o[j][2] * inv1, o[j][3] * inv1);
    }
}

// ---------------------------------------------------------------------------
extern "C" void kernel_launch(void* const* d_in, const int* in_sizes, int n_in,
                              void* d_out, int out_size)
{
    (void)in_sizes; (void)n_in; (void)out_size;
    const float* x     = (const float*)d_in[0];
    const float* w_qkv = (const float*)d_in[1];
    const float* b_qkv = (const float*)d_in[2];
    const float* w_out = (const float*)d_in[3];
    const float* b_out = (const float*)d_in[4];
    float* out = (float*)d_out;

    float* qkv  = nullptr;
    float* attn = nullptr;
    cudaGetSymbolAddress((void**)&qkv,  g_qkv);
    cudaGetSymbolAddress((void**)&attn, g_attn);

    cudaFuncSetAttribute(flash_attn_mma_kernel,
                         cudaFuncAttributeMaxDynamicSharedMemorySize, FA_SMEM);

    // 1) QKV projection: [8192,1024] @ [1024,3072] + b  (bf16x3 mma.sync)
    gemm_tc_kernel<<<dim3(QKVW / 128, NROWS / 128), 256>>>(
        x, w_qkv, b_qkv, qkv, QKVW, EMB);

    // 2) Attention per (b,h,q-tile of 128)  (bf16x3 mma.sync flash)
    flash_attn_mma_kernel<<<dim3(SEQ / 128, BATCH * HEADS), 256, FA_SMEM>>>(
        qkv, attn);

    // 3) Output projection: [8192,1024] @ [1024,1024] + b  (bf16x3 mma.sync)
    gemm_tc_kernel<<<dim3(EMB / 128, NROWS / 128), 256>>>(
        attn, w_out, b_out, out, EMB, EMB);
}

// round 9
// speedup vs baseline: 2.8989x; 1.0284x over previous
#include <cuda_runtime.h>
#include <cuda_bf16.h>
#include <cstdint>

#define EMB   1024
#define HEADS 16
#define HD    64
#define BATCH 4
#define SEQ   2048
#define NROWS (BATCH * SEQ)      // 8192
#define QKVW  (3 * EMB)          // 3072

// ---------------------------------------------------------------------------
// Global scratch: split-bf16 planes (allocation-free rule: __device__ globals)
// ---------------------------------------------------------------------------
__device__ __align__(128) uint16_t g_x_hi[(size_t)NROWS * EMB];
__device__ __align__(128) uint16_t g_x_lo[(size_t)NROWS * EMB];
__device__ __align__(128) uint16_t g_wqkv_hi[(size_t)EMB * QKVW];
__device__ __align__(128) uint16_t g_wqkv_lo[(size_t)EMB * QKVW];
__device__ __align__(128) uint16_t g_wout_hi[(size_t)EMB * EMB];
__device__ __align__(128) uint16_t g_wout_lo[(size_t)EMB * EMB];
__device__ __align__(128) uint16_t g_qkv_hi[(size_t)NROWS * QKVW];
__device__ __align__(128) uint16_t g_qkv_lo[(size_t)NROWS * QKVW];
__device__ __align__(128) uint16_t g_attn_hi[(size_t)NROWS * EMB];
__device__ __align__(128) uint16_t g_attn_lo[(size_t)NROWS * EMB];

// ---------------------------------------------------------------------------
// Helpers
// ---------------------------------------------------------------------------
__device__ __forceinline__ uint32_t smem_u32(const void* p) {
    uint32_t a;
    asm("{ .reg .u64 t; cvta.to.shared.u64 t, %1; cvt.u32.u64 %0, t; }"
        : "=r"(a) : "l"(p));
    return a;
}
// hi = truncated top-16 bits, lo = rn-bf16 of exact residual.
__device__ __forceinline__ void split_pair(float2 v, uint32_t& hi, uint32_t& lo) {
    uint32_t ax = __float_as_uint(v.x), bx = __float_as_uint(v.y);
    hi = __byte_perm(ax, bx, 0x7632);
    float lx = v.x - __uint_as_float(ax & 0xFFFF0000u);
    float ly = v.y - __uint_as_float(bx & 0xFFFF0000u);
    asm("cvt.rn.bf16x2.f32 %0, %1, %2;" : "=r"(lo) : "f"(ly), "f"(lx));
}
__device__ __forceinline__ void ldsm_x4(uint32_t* r, uint32_t addr) {
    asm volatile("ldmatrix.sync.aligned.m8n8.x4.shared.b16 {%0,%1,%2,%3}, [%4];"
                 : "=r"(r[0]), "=r"(r[1]), "=r"(r[2]), "=r"(r[3]) : "r"(addr));
}
__device__ __forceinline__ void ldsm_x4_t(uint32_t* r, uint32_t addr) {
    asm volatile("ldmatrix.sync.aligned.m8n8.x4.trans.shared.b16 {%0,%1,%2,%3}, [%4];"
                 : "=r"(r[0]), "=r"(r[1]), "=r"(r[2]), "=r"(r[3]) : "r"(addr));
}
__device__ __forceinline__ void mma_bf16(float* c, const uint32_t* a,
                                         const uint32_t* b) {
    asm volatile(
        "mma.sync.aligned.m16n8k16.row.col.f32.bf16.bf16.f32 "
        "{%0,%1,%2,%3}, {%4,%5,%6,%7}, {%8,%9}, {%0,%1,%2,%3};"
        : "+f"(c[0]), "+f"(c[1]), "+f"(c[2]), "+f"(c[3])
        : "r"(a[0]), "r"(a[1]), "r"(a[2]), "r"(a[3]), "r"(b[0]), "r"(b[1]));
}
__device__ __forceinline__ void cp16(uint32_t s, const void* g) {
    asm volatile("cp.async.cg.shared.global [%0], [%1], 16;" :: "r"(s), "l"(g));
}
__device__ __forceinline__ void cp_commit() {
    asm volatile("cp.async.commit_group;");
}
template<int N> __device__ __forceinline__ void cp_wait() {
    asm volatile("cp.async.wait_group %0;" :: "n"(N));
}

// ---------------------------------------------------------------------------
// fp32 -> split bf16 planes (one-shot converts for x / W_qkv / W_out)
// ---------------------------------------------------------------------------
__global__ void split_kernel(const float4* __restrict__ src,
                             uint16_t* __restrict__ hi,
                             uint16_t* __restrict__ lo, int n4)
{
    int i = blockIdx.x * blockDim.x + threadIdx.x;
    if (i >= n4) return;
    float4 v = src[i];
    uint32_t h0, l0, h1, l1;
    split_pair(make_float2(v.x, v.y), h0, l0);
    split_pair(make_float2(v.z, v.w), h1, l1);
    ((uint2*)hi)[i] = make_uint2(h0, h1);
    ((uint2*)lo)[i] = make_uint2(l0, l1);
}

// ===========================================================================
// GEMM v2 (pre-split bf16 inputs, 3-stage cp.async pipeline):
//   C = A @ B (+bias), A/B given as hi/lo planes; 3-term split MMA.
// 128x128 tile, K-chunk 32, 256 threads = 8 warps (4m x 2n).
// A smem [128][40] bf16 (80 B rows), B smem [32][136] bf16 (272 B rows):
// both ldmatrix-conflict-free.
// WRITE_SPLIT=1: write hi/lo planes (cols < qcols pre-scaled by 0.125).
//
// Wait discipline (R8 bug fixed): before consuming chunk kc the outstanding
// commit-groups are {G_kc, G_kc+1} -> cp_wait<1> drains G_kc; last chunk has
// only {G_nk-1} outstanding -> cp_wait<0>.
// ===========================================================================
#define G_OAH  0
#define G_OAL  10240
#define G_OBH  20480
#define G_OBL  29184
#define G_ST   37888
#define G_SMEM (3 * G_ST)   // 113664

template<int WRITE_SPLIT>
__global__ __launch_bounds__(256)
void gemm_tc2(const uint16_t* __restrict__ Ah, const uint16_t* __restrict__ Al,
              const uint16_t* __restrict__ Bh, const uint16_t* __restrict__ Bl,
              const float* __restrict__ bias,
              float* __restrict__ Cf,
              uint16_t* __restrict__ Ch, uint16_t* __restrict__ Cl,
              int N, int K, int qcols)
{
    extern __shared__ char sm[];
    const uint32_t sbase = smem_u32(sm);

    const int tid  = threadIdx.x;
    const int lane = tid & 31;
    const int wid  = tid >> 5;
    const int wm   = wid & 3;
    const int wn   = wid >> 2;
    const int row0 = blockIdx.y * 128;
    const int col0 = blockIdx.x * 128;

    // loader mappings: A 128x32 (2x16B per thread/plane), B 32x128 (2x16B)
    const int ar  = tid >> 1;
    const int akc = (tid & 1) * 2;
    const int br  = tid >> 3;
    const int bnc = (tid & 7) * 2;

    const uint16_t* Aph = Ah + (size_t)(row0 + ar) * K + akc * 8;
    const uint16_t* Apl = Al + (size_t)(row0 + ar) * K + akc * 8;
    const uint16_t* Bph = Bh + (size_t)br * N + col0 + bnc * 8;
    const uint16_t* Bpl = Bl + (size_t)br * N + col0 + bnc * 8;

    const uint32_t sao0 = (uint32_t)(ar * 40 + akc * 8) * 2u;
    const uint32_t sao1 = sao0 + 16u;
    const uint32_t sbo0 = (uint32_t)(br * 136 + bnc * 8) * 2u;
    const uint32_t sbo1 = sbo0 + 16u;

    // per-lane ldmatrix base offsets
    const int g  = lane >> 3;
    const int rr = lane & 7;
    uint32_t abase[2];
    #pragma unroll
    for (int mt = 0; mt < 2; mt++)
        abase[mt] = (uint32_t)((wm * 32 + mt * 16 + (g & 1) * 8 + rr) * 40
                               + (g >> 1) * 8) * 2u;
    uint32_t bbase[4];
    #pragma unroll
    for (int np = 0; np < 4; np++)
        bbase[np] = (uint32_t)(((g & 1) * 8 + rr) * 136
                               + wn * 64 + np * 16 + (g >> 1) * 8) * 2u;

    float acc[2][8][4];
    #pragma unroll
    for (int i = 0; i < 2; i++)
        #pragma unroll
        for (int j = 0; j < 8; j++)
            #pragma unroll
            for (int r = 0; r < 4; r++)
                acc[i][j][r] = 0.f;

    auto LOAD = [&](int st, int k0) {
        uint32_t s0 = sbase + st * G_ST;
        cp16(s0 + G_OAH + sao0, Aph + k0);
        cp16(s0 + G_OAH + sao1, Aph + k0 + 8);
        cp16(s0 + G_OAL + sao0, Apl + k0);
        cp16(s0 + G_OAL + sao1, Apl + k0 + 8);
        cp16(s0 + G_OBH + sbo0, Bph + (size_t)k0 * N);
        cp16(s0 + G_OBH + sbo1, Bph + (size_t)k0 * N + 8);
        cp16(s0 + G_OBL + sbo0, Bpl + (size_t)k0 * N);
        cp16(s0 + G_OBL + sbo1, Bpl + (size_t)k0 * N + 8);
    };

    const int nk = K / 32;   // 32
    LOAD(0, 0);  cp_commit();
    LOAD(1, 32); cp_commit();

    for (int kc = 0; kc < nk; kc++) {
        if (kc < nk - 1) cp_wait<1>();   // drain G_kc  (G_kc+1 may stay in flight)
        else             cp_wait<0>();   // last chunk: drain everything
        __syncthreads();
        if (kc + 2 < nk) { LOAD((kc + 2) % 3, (kc + 2) * 32); cp_commit(); }

        uint32_t s0 = sbase + (kc % 3) * G_ST;
        #pragma unroll
        for (int ks = 0; ks < 2; ks++) {
            const uint32_t ka = ks * 32u;     // 16 elems * 2B
            const uint32_t kb = ks * 4352u;   // 16 rows * 272B
            uint32_t ahi[2][4], alo[2][4];
            ldsm_x4(ahi[0], s0 + G_OAH + abase[0] + ka);
            ldsm_x4(ahi[1], s0 + G_OAH + abase[1] + ka);
            ldsm_x4(alo[0], s0 + G_OAL + abase[0] + ka);
            ldsm_x4(alo[1], s0 + G_OAL + abase[1] + ka);
            #pragma unroll
            for (int np = 0; np < 4; np++) {
                uint32_t bh[4], bl[4];
                ldsm_x4_t(bh, s0 + G_OBH + bbase[np] + kb);
                ldsm_x4_t(bl, s0 + G_OBL + bbase[np] + kb);
                #pragma unroll
                for (int mt = 0; mt < 2; mt++) {
                    mma_bf16(acc[mt][2 * np + 0], ahi[mt], bh);
                    mma_bf16(acc[mt][2 * np + 0], ahi[mt], bl);
                    mma_bf16(acc[mt][2 * np + 0], alo[mt], bh);
                    mma_bf16(acc[mt][2 * np + 1], ahi[mt], bh + 2);
                    mma_bf16(acc[mt][2 * np + 1], ahi[mt], bl + 2);
                    mma_bf16(acc[mt][2 * np + 1], alo[mt], bh + 2);
                }
            }
        }
        __syncthreads();   // all frag reads done before stage is overwritten
    }

    // ---- epilogue ----
    const int ml = lane >> 2;
    const int nl = 2 * (lane & 3);
    #pragma unroll
    for (int mt = 0; mt < 2; mt++) {
        #pragma unroll
        for (int nt = 0; nt < 8; nt++) {
            int m = row0 + wm * 32 + mt * 16 + ml;
            int n = col0 + wn * 64 + nt * 8 + nl;
            float2 bv = *(const float2*)&bias[n];
            float* c = acc[mt][nt];
            float v0 = c[0] + bv.x, v1 = c[1] + bv.y;
            float w0 = c[2] + bv.x, w1 = c[3] + bv.y;
            if (WRITE_SPLIT) {
                float sc = (n < qcols) ? 0.125f : 1.0f;   // fold 1/sqrt(HD) into Q
                v0 *= sc; v1 *= sc; w0 *= sc; w1 *= sc;
                uint32_t h, l;
                split_pair(make_float2(v0, v1), h, l);
                *(uint32_t*)(Ch + (size_t)m * N + n) = h;
                *(uint32_t*)(Cl + (size_t)m * N + n) = l;
                split_pair(make_float2(w0, w1), h, l);
                *(uint32_t*)(Ch + (size_t)(m + 8) * N + n) = h;
                *(uint32_t*)(Cl + (size_t)(m + 8) * N + n) = l;
            } else {
                *(float2*)(Cf + (size_t)m * N + n) = make_float2(v0, v1);
                *(float2*)(Cf + (size_t)(m + 8) * N + n) = make_float2(w0, w1);
            }
        }
    }
}

// ===========================================================================
// Flash attention, mma.sync bf16x3; Q/K/V read directly from split planes
// (no conversion, Q pre-scaled upstream); output written as split planes.
// Block = 128 q-rows x one (b,h); 256 threads, warp owns m16. K-tile 64.
// ===========================================================================
#define FA_PAD  72
#define O_QHI   0
#define O_QLO   (O_QHI + 128 * FA_PAD * 2)
#define O_KHI   (O_QLO + 128 * FA_PAD * 2)
#define O_KLO   (O_KHI + 64 * FA_PAD * 2)
#define O_VHI   (O_KLO + 64 * FA_PAD * 2)
#define O_VLO   (O_VHI + 64 * FA_PAD * 2)
#define FA_SMEM (O_VLO + 64 * FA_PAD * 2)   // 73728

__global__ __launch_bounds__(256)
void flash_attn_mma_kernel(const uint16_t* __restrict__ qkv_hi,
                           const uint16_t* __restrict__ qkv_lo,
                           uint16_t* __restrict__ attn_hi,
                           uint16_t* __restrict__ attn_lo)
{
    extern __shared__ char fsm[];
    const uint32_t sb = smem_u32(fsm);

    const int tid  = threadIdx.x;
    const int lane = tid & 31;
    const int wm   = tid >> 5;
    const int qt   = blockIdx.x;
    const int b    = blockIdx.y >> 4;
    const int h    = blockIdx.y & 15;

    // ---- load Q tile from planes (already scaled by 1/8) ----
    {
        const int r  = tid >> 1;
        const int c0 = (tid & 1) * 32;
        const uint16_t* qh = qkv_hi + (size_t)(b * SEQ + qt * 128 + r) * QKVW
                                    + h * HD + c0;
        const uint16_t* ql = qkv_lo + (size_t)(b * SEQ + qt * 128 + r) * QKVW
                                    + h * HD + c0;
        uint32_t base = (uint32_t)(r * FA_PAD + c0) * 2u;
        #pragma unroll
        for (int s = 0; s < 4; s++) {
            *(uint4*)(fsm + O_QHI + base + 16 * s) = *(const uint4*)(qh + 8 * s);
            *(uint4*)(fsm + O_QLO + base + 16 * s) = *(const uint4*)(ql + 8 * s);
        }
    }
    __syncthreads();

    // ---- preload Q fragments ----
    const int g  = lane >> 3;
    const int rr = lane & 7;
    uint32_t qhi[4][4], qlo[4][4];
    {
        uint32_t moff = (uint32_t)((wm * 16 + (g & 1) * 8 + rr) * FA_PAD) * 2u;
        #pragma unroll
        for (int t = 0; t < 4; t++) {
            uint32_t koff = (uint32_t)((g >> 1) * 8 + 16 * t) * 2u;
            ldsm_x4(qhi[t], sb + O_QHI + moff + koff);
            ldsm_x4(qlo[t], sb + O_QLO + moff + koff);
        }
    }

    const uint32_t kbase = (uint32_t)(((g >> 1) * 8 + rr) * FA_PAD + (g & 1) * 8) * 2u;
    const uint32_t vbase = (uint32_t)(((g & 1) * 8 + rr) * FA_PAD + (g >> 1) * 8) * 2u;

    float m0 = -1e30f, m1 = -1e30f, l0 = 0.f, l1 = 0.f;
    float o[8][4];
    #pragma unroll
    for (int j = 0; j < 8; j++)
        #pragma unroll
        for (int r = 0; r < 4; r++) o[j][r] = 0.f;

    const int kr  = tid >> 2;           // 0..63
    const int kc0 = (tid & 3) * 16;     // elem offset

    for (int kt = 0; kt < SEQ / 64; kt++) {
        // gather K/V plane data into registers (high MLP)
        size_t roff = (size_t)(b * SEQ + kt * 64 + kr) * QKVW + h * HD + kc0;
        const uint16_t* kh = qkv_hi + roff + EMB;
        const uint16_t* kl = qkv_lo + roff + EMB;
        const uint16_t* vh = qkv_hi + roff + 2 * EMB;
        const uint16_t* vl = qkv_lo + roff + 2 * EMB;
        uint4 kh0 = *(const uint4*)kh,       kh1 = *(const uint4*)(kh + 8);
        uint4 kl0 = *(const uint4*)kl,       kl1 = *(const uint4*)(kl + 8);
        uint4 vh0 = *(const uint4*)vh,       vh1 = *(const uint4*)(vh + 8);
        uint4 vl0 = *(const uint4*)vl,       vl1 = *(const uint4*)(vl + 8);

        __syncthreads();   // previous iteration's frag reads complete
        {
            uint32_t base = (uint32_t)(kr * FA_PAD + kc0) * 2u;
            *(uint4*)(fsm + O_KHI + base)      = kh0;
            *(uint4*)(fsm + O_KHI + base + 16) = kh1;
            *(uint4*)(fsm + O_KLO + base)      = kl0;
            *(uint4*)(fsm + O_KLO + base + 16) = kl1;
            *(uint4*)(fsm + O_VHI + base)      = vh0;
            *(uint4*)(fsm + O_VHI + base + 16) = vh1;
            *(uint4*)(fsm + O_VLO + base)      = vl0;
            *(uint4*)(fsm + O_VLO + base + 16) = vl1;
        }
        __syncthreads();

        // ---- S = Q K^T (3-term split) ----
        float s[8][4];
        #pragma unroll
        for (int j = 0; j < 8; j++)
            #pragma unroll
            for (int r4 = 0; r4 < 4; r4++) s[j][r4] = 0.f;

        #pragma unroll
        for (int nt = 0; nt < 4; nt++) {
            #pragma unroll
            for (int t = 0; t < 4; t++) {
                uint32_t off = kbase + (uint32_t)(nt * 16 * FA_PAD + 16 * t) * 2u;
                uint32_t kfh[4], kfl[4];
                ldsm_x4(kfh, sb + O_KHI + off);
                ldsm_x4(kfl, sb + O_KLO + off);
                mma_bf16(s[2*nt + 0], qhi[t], kfh);
                mma_bf16(s[2*nt + 0], qhi[t], kfl);
                mma_bf16(s[2*nt + 0], qlo[t], kfh);
                mma_bf16(s[2*nt + 1], qhi[t], kfh + 2);
                mma_bf16(s[2*nt + 1], qhi[t], kfl + 2);
                mma_bf16(s[2*nt + 1], qlo[t], kfh + 2);
            }
        }

        // ---- online softmax ----
        float mx0 = -1e30f, mx1 = -1e30f;
        #pragma unroll
        for (int j = 0; j < 8; j++) {
            mx0 = fmaxf(mx0, fmaxf(s[j][0], s[j][1]));
            mx1 = fmaxf(mx1, fmaxf(s[j][2], s[j][3]));
        }
        mx0 = fmaxf(mx0, __shfl_xor_sync(0xffffffffu, mx0, 1));
        mx0 = fmaxf(mx0, __shfl_xor_sync(0xffffffffu, mx0, 2));
        mx1 = fmaxf(mx1, __shfl_xor_sync(0xffffffffu, mx1, 1));
        mx1 = fmaxf(mx1, __shfl_xor_sync(0xffffffffu, mx1, 2));

        float mn0 = fmaxf(m0, mx0), mn1 = fmaxf(m1, mx1);
        float a0 = __expf(m0 - mn0), a1 = __expf(m1 - mn1);
        m0 = mn0; m1 = mn1;

        float sum0 = 0.f, sum1 = 0.f;
        #pragma unroll
        for (int j = 0; j < 8; j++) {
            s[j][0] = __expf(s[j][0] - mn0);
            s[j][1] = __expf(s[j][1] - mn0);
            s[j][2] = __expf(s[j][2] - mn1);
            s[j][3] = __expf(s[j][3] - mn1);
            sum0 += s[j][0] + s[j][1];
            sum1 += s[j][2] + s[j][3];
        }
        sum0 += __shfl_xor_sync(0xffffffffu, sum0, 1);
        sum0 += __shfl_xor_sync(0xffffffffu, sum0, 2);
        sum1 += __shfl_xor_sync(0xffffffffu, sum1, 1);
        sum1 += __shfl_xor_sync(0xffffffffu, sum1, 2);
        l0 = l0 * a0 + sum0;
        l1 = l1 * a1 + sum1;

        #pragma unroll
        for (int j = 0; j < 8; j++) {
            o[j][0] *= a0; o[j][1] *= a0;
            o[j][2] *= a1; o[j][3] *= a1;
        }

        // ---- o += P V (3-term split, P frags in-register) ----
        #pragma unroll
        for (int t = 0; t < 4; t++) {
            uint32_t phi[4], plo[4];
            split_pair(make_float2(s[2*t][0],   s[2*t][1]),   phi[0], plo[0]);
            split_pair(make_float2(s[2*t][2],   s[2*t][3]),   phi[1], plo[1]);
            split_pair(make_float2(s[2*t+1][0], s[2*t+1][1]), phi[2], plo[2]);
            split_pair(make_float2(s[2*t+1][2], s[2*t+1][3]), phi[3], plo[3]);
            #pragma unroll
            for (int nt = 0; nt < 4; nt++) {
                uint32_t off = vbase + (uint32_t)(t * 16 * FA_PAD + nt * 16) * 2u;
                uint32_t vfh[4], vfl[4];
                ldsm_x4_t(vfh, sb + O_VHI + off);
                ldsm_x4_t(vfl, sb + O_VLO + off);
                mma_bf16(o[2*nt + 0], phi, vfh);
                mma_bf16(o[2*nt + 0], phi, vfl);
                mma_bf16(o[2*nt + 0], plo, vfh);
                mma_bf16(o[2*nt + 1], phi, vfh + 2);
                mma_bf16(o[2*nt + 1], phi, vfl + 2);
                mma_bf16(o[2*nt + 1], plo, vfh + 2);
            }
        }
    }

    // ---- epilogue: normalize, split, write planes ----
    float inv0 = 1.f / l0, inv1 = 1.f / l1;
    int row = b * SEQ + qt * 128 + wm * 16 + (lane >> 2);
    size_t e0 = (size_t)row * EMB + h * HD + 2 * (lane & 3);
    #pragma unroll
    for (int j = 0; j < 8; j++) {
        uint32_t hh, ll;
        split_pair(make_float2(o[j][0] * inv0, o[j][1] * inv0), hh, ll);
        *(uint32_t*)(attn_hi + e0 + 8 * j) = hh;
        *(uint32_t*)(attn_lo + e0 + 8 * j) = ll;
        split_pair(make_float2(o[j][2] * inv1, o[j][3] * inv1), hh, ll);
        *(uint32_t*)(attn_hi + e0 + (size_t)8 * EMB + 8 * j) = hh;
        *(uint32_t*)(attn_lo + e0 + (size_t)8 * EMB + 8 * j) = ll;
    }
}

// ---------------------------------------------------------------------------
extern "C" void kernel_launch(void* const* d_in, const int* in_sizes, int n_in,
                              void* d_out, int out_size)
{
    (void)in_sizes; (void)n_in; (void)out_size;
    const float* x     = (const float*)d_in[0];
    const float* w_qkv = (const float*)d_in[1];
    const float* b_qkv = (const float*)d_in[2];
    const float* w_out = (const float*)d_in[3];
    const float* b_out = (const float*)d_in[4];
    float* out = (float*)d_out;

    uint16_t *x_hi, *x_lo, *wq_hi, *wq_lo, *wo_hi, *wo_lo;
    uint16_t *qkv_hi, *qkv_lo, *attn_hi, *attn_lo;
    cudaGetSymbolAddress((void**)&x_hi,   g_x_hi);
    cudaGetSymbolAddress((void**)&x_lo,   g_x_lo);
    cudaGetSymbolAddress((void**)&wq_hi,  g_wqkv_hi);
    cudaGetSymbolAddress((void**)&wq_lo,  g_wqkv_lo);
    cudaGetSymbolAddress((void**)&wo_hi,  g_wout_hi);
    cudaGetSymbolAddress((void**)&wo_lo,  g_wout_lo);
    cudaGetSymbolAddress((void**)&qkv_hi, g_qkv_hi);
    cudaGetSymbolAddress((void**)&qkv_lo, g_qkv_lo);
    cudaGetSymbolAddress((void**)&attn_hi, g_attn_hi);
    cudaGetSymbolAddress((void**)&attn_lo, g_attn_lo);

    cudaFuncSetAttribute(gemm_tc2<1>,
                         cudaFuncAttributeMaxDynamicSharedMemorySize, G_SMEM);
    cudaFuncSetAttribute(gemm_tc2<0>,
                         cudaFuncAttributeMaxDynamicSharedMemorySize, G_SMEM);
    cudaFuncSetAttribute(flash_attn_mma_kernel,
                         cudaFuncAttributeMaxDynamicSharedMemorySize, FA_SMEM);

    // 0) one-shot splits of inputs
    split_kernel<<<(NROWS * EMB / 4) / 256, 256>>>(
        (const float4*)x, x_hi, x_lo, NROWS * EMB / 4);
    split_kernel<<<(EMB * QKVW / 4) / 256, 256>>>(
        (const float4*)w_qkv, wq_hi, wq_lo, EMB * QKVW / 4);
    split_kernel<<<(EMB * EMB / 4) / 256, 256>>>(
        (const float4*)w_out, wo_hi, wo_lo, EMB * EMB / 4);

    // 1) QKV projection -> split planes (Q cols pre-scaled by 1/8)
    gemm_tc2<1><<<dim3(QKVW / 128, NROWS / 128), 256, G_SMEM>>>(
        x_hi, x_lo, wq_hi, wq_lo, b_qkv, nullptr, qkv_hi, qkv_lo,
        QKVW, EMB, EMB);

    // 2) attention -> split planes
    flash_attn_mma_kernel<<<dim3(SEQ / 128, BATCH * HEADS), 256, FA_SMEM>>>(
        qkv_hi, qkv_lo, attn_hi, attn_lo);

    // 3) output projection -> fp32 out
    gemm_tc2<0><<<dim3(EMB / 128, NROWS / 128), 256, G_SMEM>>>(
        attn_hi, attn_lo, wo_hi, wo_lo, b_out, out, nullptr, nullptr,
        EMB, EMB, 0);
}

// round 10
// speedup vs baseline: 3.2070x; 1.1063x over previous
#include <cuda_runtime.h>
#include <cuda_bf16.h>
#include <cstdint>

#define EMB   1024
#define HEADS 16
#define HD    64
#define BATCH 4
#define SEQ   2048
#define NROWS (BATCH * SEQ)      // 8192
#define QKVW  (3 * EMB)          // 3072

// ---------------------------------------------------------------------------
// Global scratch: split-bf16 planes (allocation-free rule: __device__ globals)
// ---------------------------------------------------------------------------
__device__ __align__(128) uint16_t g_x_hi[(size_t)NROWS * EMB];
__device__ __align__(128) uint16_t g_x_lo[(size_t)NROWS * EMB];
__device__ __align__(128) uint16_t g_wqkv_hi[(size_t)EMB * QKVW];
__device__ __align__(128) uint16_t g_wqkv_lo[(size_t)EMB * QKVW];
__device__ __align__(128) uint16_t g_wout_hi[(size_t)EMB * EMB];
__device__ __align__(128) uint16_t g_wout_lo[(size_t)EMB * EMB];
__device__ __align__(128) uint16_t g_qkv_hi[(size_t)NROWS * QKVW];
__device__ __align__(128) uint16_t g_qkv_lo[(size_t)NROWS * QKVW];
__device__ __align__(128) uint16_t g_attn_hi[(size_t)NROWS * EMB];
__device__ __align__(128) uint16_t g_attn_lo[(size_t)NROWS * EMB];

// ---------------------------------------------------------------------------
// Helpers
// ---------------------------------------------------------------------------
__device__ __forceinline__ uint32_t smem_u32(const void* p) {
    uint32_t a;
    asm("{ .reg .u64 t; cvta.to.shared.u64 t, %1; cvt.u32.u64 %0, t; }"
        : "=r"(a) : "l"(p));
    return a;
}
// hi = truncated top-16 bits, lo = rn-bf16 of exact residual.
__device__ __forceinline__ void split_pair(float2 v, uint32_t& hi, uint32_t& lo) {
    uint32_t ax = __float_as_uint(v.x), bx = __float_as_uint(v.y);
    hi = __byte_perm(ax, bx, 0x7632);
    float lx = v.x - __uint_as_float(ax & 0xFFFF0000u);
    float ly = v.y - __uint_as_float(bx & 0xFFFF0000u);
    asm("cvt.rn.bf16x2.f32 %0, %1, %2;" : "=r"(lo) : "f"(ly), "f"(lx));
}
__device__ __forceinline__ void ldsm_x4(uint32_t* r, uint32_t addr) {
    asm volatile("ldmatrix.sync.aligned.m8n8.x4.shared.b16 {%0,%1,%2,%3}, [%4];"
                 : "=r"(r[0]), "=r"(r[1]), "=r"(r[2]), "=r"(r[3]) : "r"(addr));
}
__device__ __forceinline__ void ldsm_x4_t(uint32_t* r, uint32_t addr) {
    asm volatile("ldmatrix.sync.aligned.m8n8.x4.trans.shared.b16 {%0,%1,%2,%3}, [%4];"
                 : "=r"(r[0]), "=r"(r[1]), "=r"(r[2]), "=r"(r[3]) : "r"(addr));
}
__device__ __forceinline__ void mma_bf16(float* c, const uint32_t* a,
                                         const uint32_t* b) {
    asm volatile(
        "mma.sync.aligned.m16n8k16.row.col.f32.bf16.bf16.f32 "
        "{%0,%1,%2,%3}, {%4,%5,%6,%7}, {%8,%9}, {%0,%1,%2,%3};"
        : "+f"(c[0]), "+f"(c[1]), "+f"(c[2]), "+f"(c[3])
        : "r"(a[0]), "r"(a[1]), "r"(a[2]), "r"(a[3]), "r"(b[0]), "r"(b[1]));
}
__device__ __forceinline__ void cp16(uint32_t s, const void* g) {
    asm volatile("cp.async.cg.shared.global [%0], [%1], 16;" :: "r"(s), "l"(g));
}
__device__ __forceinline__ void cp_commit() {
    asm volatile("cp.async.commit_group;");
}
template<int N> __device__ __forceinline__ void cp_wait() {
    asm volatile("cp.async.wait_group %0;" :: "n"(N));
}

// ---------------------------------------------------------------------------
// fp32 -> split bf16 planes (one-shot converts for x / W_qkv / W_out)
// ---------------------------------------------------------------------------
__global__ void split_kernel(const float4* __restrict__ src,
                             uint16_t* __restrict__ hi,
                             uint16_t* __restrict__ lo, int n4)
{
    int i = blockIdx.x * blockDim.x + threadIdx.x;
    if (i >= n4) return;
    float4 v = src[i];
    uint32_t h0, l0, h1, l1;
    split_pair(make_float2(v.x, v.y), h0, l0);
    split_pair(make_float2(v.z, v.w), h1, l1);
    ((uint2*)hi)[i] = make_uint2(h0, h1);
    ((uint2*)lo)[i] = make_uint2(l0, l1);
}

// ===========================================================================
// GEMM v3: pre-split bf16 inputs, 2-stage cp.async double buffer,
// 2 CTAs/SM (smem 75776 B total, regs forced <=128).
// 128x128 tile, K-chunk 32, 256 threads = 8 warps (4m x 2n).
// A smem [128][40] bf16, B smem [32][136] bf16: ldmatrix-conflict-free.
// WRITE_SPLIT=1: write hi/lo planes (cols < qcols pre-scaled by 0.125).
//
// Wait discipline: before consuming chunk kc the outstanding groups are
// {G_kc, G_kc+1} -> cp_wait<1>; last chunk -> cp_wait<0>. Load of kc+2 is
// issued AFTER the compute of kc (it reuses stage kc%2), overlapping the
// compute of kc+1.
// ===========================================================================
#define G_OAH  0
#define G_OAL  10240
#define G_OBH  20480
#define G_OBL  29184
#define G_ST   37888
#define G_SMEM (2 * G_ST)   // 75776 -> 2 CTAs/SM

template<int WRITE_SPLIT>
__global__ __launch_bounds__(256, 2)
void gemm_tc2(const uint16_t* __restrict__ Ah, const uint16_t* __restrict__ Al,
              const uint16_t* __restrict__ Bh, const uint16_t* __restrict__ Bl,
              const float* __restrict__ bias,
              float* __restrict__ Cf,
              uint16_t* __restrict__ Ch, uint16_t* __restrict__ Cl,
              int N, int K, int qcols)
{
    extern __shared__ char sm[];
    const uint32_t sbase = smem_u32(sm);

    const int tid  = threadIdx.x;
    const int lane = tid & 31;
    const int wid  = tid >> 5;
    const int wm   = wid & 3;
    const int wn   = wid >> 2;
    const int row0 = blockIdx.y * 128;
    const int col0 = blockIdx.x * 128;

    // loader mappings: A 128x32 (2x16B per thread/plane), B 32x128 (2x16B)
    const int ar  = tid >> 1;
    const int akc = (tid & 1) * 2;
    const int br  = tid >> 3;
    const int bnc = (tid & 7) * 2;

    const uint16_t* Aph = Ah + (size_t)(row0 + ar) * K + akc * 8;
    const uint16_t* Apl = Al + (size_t)(row0 + ar) * K + akc * 8;
    const uint16_t* Bph = Bh + (size_t)br * N + col0 + bnc * 8;
    const uint16_t* Bpl = Bl + (size_t)br * N + col0 + bnc * 8;

    const uint32_t sao0 = (uint32_t)(ar * 40 + akc * 8) * 2u;
    const uint32_t sao1 = sao0 + 16u;
    const uint32_t sbo0 = (uint32_t)(br * 136 + bnc * 8) * 2u;
    const uint32_t sbo1 = sbo0 + 16u;

    // per-lane ldmatrix base offsets
    const int g  = lane >> 3;
    const int rr = lane & 7;
    uint32_t abase[2];
    #pragma unroll
    for (int mt = 0; mt < 2; mt++)
        abase[mt] = (uint32_t)((wm * 32 + mt * 16 + (g & 1) * 8 + rr) * 40
                               + (g >> 1) * 8) * 2u;
    uint32_t bbase[4];
    #pragma unroll
    for (int np = 0; np < 4; np++)
        bbase[np] = (uint32_t)(((g & 1) * 8 + rr) * 136
                               + wn * 64 + np * 16 + (g >> 1) * 8) * 2u;

    float acc[2][8][4];
    #pragma unroll
    for (int i = 0; i < 2; i++)
        #pragma unroll
        for (int j = 0; j < 8; j++)
            #pragma unroll
            for (int r = 0; r < 4; r++)
                acc[i][j][r] = 0.f;

    auto LOAD = [&](int st, int k0) {
        uint32_t s0 = sbase + st * G_ST;
        cp16(s0 + G_OAH + sao0, Aph + k0);
        cp16(s0 + G_OAH + sao1, Aph + k0 + 8);
        cp16(s0 + G_OAL + sao0, Apl + k0);
        cp16(s0 + G_OAL + sao1, Apl + k0 + 8);
        cp16(s0 + G_OBH + sbo0, Bph + (size_t)k0 * N);
        cp16(s0 + G_OBH + sbo1, Bph + (size_t)k0 * N + 8);
        cp16(s0 + G_OBL + sbo0, Bpl + (size_t)k0 * N);
        cp16(s0 + G_OBL + sbo1, Bpl + (size_t)k0 * N + 8);
    };

    const int nk = K / 32;   // 32
    LOAD(0, 0);  cp_commit();
    LOAD(1, 32); cp_commit();

    for (int kc = 0; kc < nk; kc++) {
        if (kc < nk - 1) cp_wait<1>();   // drain G_kc
        else             cp_wait<0>();
        __syncthreads();

        uint32_t s0 = sbase + (kc & 1) * G_ST;
        #pragma unroll
        for (int ks = 0; ks < 2; ks++) {
            const uint32_t ka = ks * 32u;     // 16 elems * 2B
            const uint32_t kb = ks * 4352u;   // 16 rows * 272B
            uint32_t ahi[2][4], alo[2][4];
            ldsm_x4(ahi[0], s0 + G_OAH + abase[0] + ka);
            ldsm_x4(ahi[1], s0 + G_OAH + abase[1] + ka);
            ldsm_x4(alo[0], s0 + G_OAL + abase[0] + ka);
            ldsm_x4(alo[1], s0 + G_OAL + abase[1] + ka);
            #pragma unroll
            for (int np = 0; np < 4; np++) {
                uint32_t bh[4], bl[4];
                ldsm_x4_t(bh, s0 + G_OBH + bbase[np] + kb);
                ldsm_x4_t(bl, s0 + G_OBL + bbase[np] + kb);
                #pragma unroll
                for (int mt = 0; mt < 2; mt++) {
                    mma_bf16(acc[mt][2 * np + 0], ahi[mt], bh);
                    mma_bf16(acc[mt][2 * np + 0], ahi[mt], bl);
                    mma_bf16(acc[mt][2 * np + 0], alo[mt], bh);
                    mma_bf16(acc[mt][2 * np + 1], ahi[mt], bh + 2);
                    mma_bf16(acc[mt][2 * np + 1], ahi[mt], bl + 2);
                    mma_bf16(acc[mt][2 * np + 1], alo[mt], bh + 2);
                }
            }
        }
        __syncthreads();   // stage (kc&1) fully consumed
        if (kc + 2 < nk) { LOAD(kc & 1, (kc + 2) * 32); cp_commit(); }
    }

    // ---- epilogue ----
    const int ml = lane >> 2;
    const int nl = 2 * (lane & 3);
    #pragma unroll
    for (int mt = 0; mt < 2; mt++) {
        #pragma unroll
        for (int nt = 0; nt < 8; nt++) {
            int m = row0 + wm * 32 + mt * 16 + ml;
            int n = col0 + wn * 64 + nt * 8 + nl;
            float2 bv = *(const float2*)&bias[n];
            float* c = acc[mt][nt];
            float v0 = c[0] + bv.x, v1 = c[1] + bv.y;
            float w0 = c[2] + bv.x, w1 = c[3] + bv.y;
            if (WRITE_SPLIT) {
                float sc = (n < qcols) ? 0.125f : 1.0f;   // fold 1/sqrt(HD) into Q
                v0 *= sc; v1 *= sc; w0 *= sc; w1 *= sc;
                uint32_t h, l;
                split_pair(make_float2(v0, v1), h, l);
                *(uint32_t*)(Ch + (size_t)m * N + n) = h;
                *(uint32_t*)(Cl + (size_t)m * N + n) = l;
                split_pair(make_float2(w0, w1), h, l);
                *(uint32_t*)(Ch + (size_t)(m + 8) * N + n) = h;
                *(uint32_t*)(Cl + (size_t)(m + 8) * N + n) = l;
            } else {
                *(float2*)(Cf + (size_t)m * N + n) = make_float2(v0, v1);
                *(float2*)(Cf + (size_t)(m + 8) * N + n) = make_float2(w0, w1);
            }
        }
    }
}

// ===========================================================================
// Flash attention, mma.sync bf16x3; Q/K/V read directly from split planes
// (no conversion, Q pre-scaled upstream); output written as split planes.
// Block = 128 q-rows x one (b,h); 256 threads, warp owns m16. K-tile 64.
// (unchanged from R9)
// ===========================================================================
#define FA_PAD  72
#define O_QHI   0
#define O_QLO   (O_QHI + 128 * FA_PAD * 2)
#define O_KHI   (O_QLO + 128 * FA_PAD * 2)
#define O_KLO   (O_KHI + 64 * FA_PAD * 2)
#define O_VHI   (O_KLO + 64 * FA_PAD * 2)
#define O_VLO   (O_VHI + 64 * FA_PAD * 2)
#define FA_SMEM (O_VLO + 64 * FA_PAD * 2)   // 73728

__global__ __launch_bounds__(256)
void flash_attn_mma_kernel(const uint16_t* __restrict__ qkv_hi,
                           const uint16_t* __restrict__ qkv_lo,
                           uint16_t* __restrict__ attn_hi,
                           uint16_t* __restrict__ attn_lo)
{
    extern __shared__ char fsm[];
    const uint32_t sb = smem_u32(fsm);

    const int tid  = threadIdx.x;
    const int lane = tid & 31;
    const int wm   = tid >> 5;
    const int qt   = blockIdx.x;
    const int b    = blockIdx.y >> 4;
    const int h    = blockIdx.y & 15;

    // ---- load Q tile from planes (already scaled by 1/8) ----
    {
        const int r  = tid >> 1;
        const int c0 = (tid & 1) * 32;
        const uint16_t* qh = qkv_hi + (size_t)(b * SEQ + qt * 128 + r) * QKVW
                                    + h * HD + c0;
        const uint16_t* ql = qkv_lo + (size_t)(b * SEQ + qt * 128 + r) * QKVW
                                    + h * HD + c0;
        uint32_t base = (uint32_t)(r * FA_PAD + c0) * 2u;
        #pragma unroll
        for (int s = 0; s < 4; s++) {
            *(uint4*)(fsm + O_QHI + base + 16 * s) = *(const uint4*)(qh + 8 * s);
            *(uint4*)(fsm + O_QLO + base + 16 * s) = *(const uint4*)(ql + 8 * s);
        }
    }
    __syncthreads();

    // ---- preload Q fragments ----
    const int g  = lane >> 3;
    const int rr = lane & 7;
    uint32_t qhi[4][4], qlo[4][4];
    {
        uint32_t moff = (uint32_t)((wm * 16 + (g & 1) * 8 + rr) * FA_PAD) * 2u;
        #pragma unroll
        for (int t = 0; t < 4; t++) {
            uint32_t koff = (uint32_t)((g >> 1) * 8 + 16 * t) * 2u;
            ldsm_x4(qhi[t], sb + O_QHI + moff + koff);
            ldsm_x4(qlo[t], sb + O_QLO + moff + koff);
        }
    }

    const uint32_t kbase = (uint32_t)(((g >> 1) * 8 + rr) * FA_PAD + (g & 1) * 8) * 2u;
    const uint32_t vbase = (uint32_t)(((g & 1) * 8 + rr) * FA_PAD + (g >> 1) * 8) * 2u;

    float m0 = -1e30f, m1 = -1e30f, l0 = 0.f, l1 = 0.f;
    float o[8][4];
    #pragma unroll
    for (int j = 0; j < 8; j++)
        #pragma unroll
        for (int r = 0; r < 4; r++) o[j][r] = 0.f;

    const int kr  = tid >> 2;           // 0..63
    const int kc0 = (tid & 3) * 16;     // elem offset

    for (int kt = 0; kt < SEQ / 64; kt++) {
        // gather K/V plane data into registers (high MLP)
        size_t roff = (size_t)(b * SEQ + kt * 64 + kr) * QKVW + h * HD + kc0;
        const uint16_t* kh = qkv_hi + roff + EMB;
        const uint16_t* kl = qkv_lo + roff + EMB;
        const uint16_t* vh = qkv_hi + roff + 2 * EMB;
        const uint16_t* vl = qkv_lo + roff + 2 * EMB;
        uint4 kh0 = *(const uint4*)kh,       kh1 = *(const uint4*)(kh + 8);
        uint4 kl0 = *(const uint4*)kl,       kl1 = *(const uint4*)(kl + 8);
        uint4 vh0 = *(const uint4*)vh,       vh1 = *(const uint4*)(vh + 8);
        uint4 vl0 = *(const uint4*)vl,       vl1 = *(const uint4*)(vl + 8);

        __syncthreads();   // previous iteration's frag reads complete
        {
            uint32_t base = (uint32_t)(kr * FA_PAD + kc0) * 2u;
            *(uint4*)(fsm + O_KHI + base)      = kh0;
            *(uint4*)(fsm + O_KHI + base + 16) = kh1;
            *(uint4*)(fsm + O_KLO + base)      = kl0;
            *(uint4*)(fsm + O_KLO + base + 16) = kl1;
            *(uint4*)(fsm + O_VHI + base)      = vh0;
            *(uint4*)(fsm + O_VHI + base + 16) = vh1;
            *(uint4*)(fsm + O_VLO + base)      = vl0;
            *(uint4*)(fsm + O_VLO + base + 16) = vl1;
        }
        __syncthreads();

        // ---- S = Q K^T (3-term split) ----
        float s[8][4];
        #pragma unroll
        for (int j = 0; j < 8; j++)
            #pragma unroll
            for (int r4 = 0; r4 < 4; r4++) s[j][r4] = 0.f;

        #pragma unroll
        for (int nt = 0; nt < 4; nt++) {
            #pragma unroll
            for (int t = 0; t < 4; t++) {
                uint32_t off = kbase + (uint32_t)(nt * 16 * FA_PAD + 16 * t) * 2u;
                uint32_t kfh[4], kfl[4];
                ldsm_x4(kfh, sb + O_KHI + off);
                ldsm_x4(kfl, sb + O_KLO + off);
                mma_bf16(s[2*nt + 0], qhi[t], kfh);
                mma_bf16(s[2*nt + 0], qhi[t], kfl);
                mma_bf16(s[2*nt + 0], qlo[t], kfh);
                mma_bf16(s[2*nt + 1], qhi[t], kfh + 2);
                mma_bf16(s[2*nt + 1], qhi[t], kfl + 2);
                mma_bf16(s[2*nt + 1], qlo[t], kfh + 2);
            }
        }

        // ---- online softmax ----
        float mx0 = -1e30f, mx1 = -1e30f;
        #pragma unroll
        for (int j = 0; j < 8; j++) {
            mx0 = fmaxf(mx0, fmaxf(s[j][0], s[j][1]));
            mx1 = fmaxf(mx1, fmaxf(s[j][2], s[j][3]));
        }
        mx0 = fmaxf(mx0, __shfl_xor_sync(0xffffffffu, mx0, 1));
        mx0 = fmaxf(mx0, __shfl_xor_sync(0xffffffffu, mx0, 2));
        mx1 = fmaxf(mx1, __shfl_xor_sync(0xffffffffu, mx1, 1));
        mx1 = fmaxf(mx1, __shfl_xor_sync(0xffffffffu, mx1, 2));

        float mn0 = fmaxf(m0, mx0), mn1 = fmaxf(m1, mx1);
        float a0 = __expf(m0 - mn0), a1 = __expf(m1 - mn1);
        m0 = mn0; m1 = mn1;

        float sum0 = 0.f, sum1 = 0.f;
        #pragma unroll
        for (int j = 0; j < 8; j++) {
            s[j][0] = __expf(s[j][0] - mn0);
            s[j][1] = __expf(s[j][1] - mn0);
            s[j][2] = __expf(s[j][2] - mn1);
            s[j][3] = __expf(s[j][3] - mn1);
            sum0 += s[j][0] + s[j][1];
            sum1 += s[j][2] + s[j][3];
        }
        sum0 += __shfl_xor_sync(0xffffffffu, sum0, 1);
        sum0 += __shfl_xor_sync(0xffffffffu, sum0, 2);
        sum1 += __shfl_xor_sync(0xffffffffu, sum1, 1);
        sum1 += __shfl_xor_sync(0xffffffffu, sum1, 2);
        l0 = l0 * a0 + sum0;
        l1 = l1 * a1 + sum1;

        #pragma unroll
        for (int j = 0; j < 8; j++) {
            o[j][0] *= a0; o[j][1] *= a0;
            o[j][2] *= a1; o[j][3] *= a1;
        }

        // ---- o += P V (3-term split, P frags in-register) ----
        #pragma unroll
        for (int t = 0; t < 4; t++) {
            uint32_t phi[4], plo[4];
            split_pair(make_float2(s[2*t][0],   s[2*t][1]),   phi[0], plo[0]);
            split_pair(make_float2(s[2*t][2],   s[2*t][3]),   phi[1], plo[1]);
            split_pair(make_float2(s[2*t+1][0], s[2*t+1][1]), phi[2], plo[2]);
            split_pair(make_float2(s[2*t+1][2], s[2*t+1][3]), phi[3], plo[3]);
            #pragma unroll
            for (int nt = 0; nt < 4; nt++) {
                uint32_t off = vbase + (uint32_t)(t * 16 * FA_PAD + nt * 16) * 2u;
                uint32_t vfh[4], vfl[4];
                ldsm_x4_t(vfh, sb + O_VHI + off);
                ldsm_x4_t(vfl, sb + O_VLO + off);
                mma_bf16(o[2*nt + 0], phi, vfh);
                mma_bf16(o[2*nt + 0], phi, vfl);
                mma_bf16(o[2*nt + 0], plo, vfh);
                mma_bf16(o[2*nt + 1], phi, vfh + 2);
                mma_bf16(o[2*nt + 1], phi, vfl + 2);
                mma_bf16(o[2*nt + 1], plo, vfh + 2);
            }
        }
    }

    // ---- epilogue: normalize, split, write planes ----
    float inv0 = 1.f / l0, inv1 = 1.f / l1;
    int row = b * SEQ + qt * 128 + wm * 16 + (lane >> 2);
    size_t e0 = (size_t)row * EMB + h * HD + 2 * (lane & 3);
    #pragma unroll
    for (int j = 0; j < 8; j++) {
        uint32_t hh, ll;
        split_pair(make_float2(o[j][0] * inv0, o[j][1] * inv0), hh, ll);
        *(uint32_t*)(attn_hi + e0 + 8 * j) = hh;
        *(uint32_t*)(attn_lo + e0 + 8 * j) = ll;
        split_pair(make_float2(o[j][2] * inv1, o[j][3] * inv1), hh, ll);
        *(uint32_t*)(attn_hi + e0 + (size_t)8 * EMB + 8 * j) = hh;
        *(uint32_t*)(attn_lo + e0 + (size_t)8 * EMB + 8 * j) = ll;
    }
}

// ---------------------------------------------------------------------------
extern "C" void kernel_launch(void* const* d_in, const int* in_sizes, int n_in,
                              void* d_out, int out_size)
{
    (void)in_sizes; (void)n_in; (void)out_size;
    const float* x     = (const float*)d_in[0];
    const float* w_qkv = (const float*)d_in[1];
    const float* b_qkv = (const float*)d_in[2];
    const float* w_out = (const float*)d_in[3];
    const float* b_out = (const float*)d_in[4];
    float* out = (float*)d_out;

    uint16_t *x_hi, *x_lo, *wq_hi, *wq_lo, *wo_hi, *wo_lo;
    uint16_t *qkv_hi, *qkv_lo, *attn_hi, *attn_lo;
    cudaGetSymbolAddress((void**)&x_hi,   g_x_hi);
    cudaGetSymbolAddress((void**)&x_lo,   g_x_lo);
    cudaGetSymbolAddress((void**)&wq_hi,  g_wqkv_hi);
    cudaGetSymbolAddress((void**)&wq_lo,  g_wqkv_lo);
    cudaGetSymbolAddress((void**)&wo_hi,  g_wout_hi);
    cudaGetSymbolAddress((void**)&wo_lo,  g_wout_lo);
    cudaGetSymbolAddress((void**)&qkv_hi, g_qkv_hi);
    cudaGetSymbolAddress((void**)&qkv_lo, g_qkv_lo);
    cudaGetSymbolAddress((void**)&attn_hi, g_attn_hi);
    cudaGetSymbolAddress((void**)&attn_lo, g_attn_lo);

    cudaFuncSetAttribute(gemm_tc2<1>,
                         cudaFuncAttributeMaxDynamicSharedMemorySize, G_SMEM);
    cudaFuncSetAttribute(gemm_tc2<0>,
                         cudaFuncAttributeMaxDynamicSharedMemorySize, G_SMEM);
    cudaFuncSetAttribute(flash_attn_mma_kernel,
                         cudaFuncAttributeMaxDynamicSharedMemorySize, FA_SMEM);

    // 0) one-shot splits of inputs
    split_kernel<<<(NROWS * EMB / 4) / 256, 256>>>(
        (const float4*)x, x_hi, x_lo, NROWS * EMB / 4);
    split_kernel<<<(EMB * QKVW / 4) / 256, 256>>>(
        (const float4*)w_qkv, wq_hi, wq_lo, EMB * QKVW / 4);
    split_kernel<<<(EMB * EMB / 4) / 256, 256>>>(
        (const float4*)w_out, wo_hi, wo_lo, EMB * EMB / 4);

    // 1) QKV projection -> split planes (Q cols pre-scaled by 1/8)
    gemm_tc2<1><<<dim3(QKVW / 128, NROWS / 128), 256, G_SMEM>>>(
        x_hi, x_lo, wq_hi, wq_lo, b_qkv, nullptr, qkv_hi, qkv_lo,
        QKVW, EMB, EMB);

    // 2) attention -> split planes
    flash_attn_mma_kernel<<<dim3(SEQ / 128, BATCH * HEADS), 256, FA_SMEM>>>(
        qkv_hi, qkv_lo, attn_hi, attn_lo);

    // 3) output projection -> fp32 out
    gemm_tc2<0><<<dim3(EMB / 128, NROWS / 128), 256, G_SMEM>>>(
        attn_hi, attn_lo, wo_hi, wo_lo, b_out, out, nullptr, nullptr,
        EMB, EMB, 0);
}

// round 11
// speedup vs baseline: 3.4059x; 1.0620x over previous
#include <cuda_runtime.h>
#include <cuda_bf16.h>
#include <cstdint>

#define EMB   1024
#define HEADS 16
#define HD    64
#define BATCH 4
#define SEQ   2048
#define NROWS (BATCH * SEQ)      // 8192
#define QKVW  (3 * EMB)          // 3072

// ---------------------------------------------------------------------------
// Global scratch: split-bf16 planes (allocation-free rule: __device__ globals)
// ---------------------------------------------------------------------------
__device__ __align__(128) uint16_t g_x_hi[(size_t)NROWS * EMB];
__device__ __align__(128) uint16_t g_x_lo[(size_t)NROWS * EMB];
__device__ __align__(128) uint16_t g_wqkv_hi[(size_t)EMB * QKVW];
__device__ __align__(128) uint16_t g_wqkv_lo[(size_t)EMB * QKVW];
__device__ __align__(128) uint16_t g_wout_hi[(size_t)EMB * EMB];
__device__ __align__(128) uint16_t g_wout_lo[(size_t)EMB * EMB];
__device__ __align__(128) uint16_t g_qkv_hi[(size_t)NROWS * QKVW];
__device__ __align__(128) uint16_t g_qkv_lo[(size_t)NROWS * QKVW];
__device__ __align__(128) uint16_t g_attn_hi[(size_t)NROWS * EMB];
__device__ __align__(128) uint16_t g_attn_lo[(size_t)NROWS * EMB];

// ---------------------------------------------------------------------------
// Helpers
// ---------------------------------------------------------------------------
__device__ __forceinline__ uint32_t smem_u32(const void* p) {
    uint32_t a;
    asm("{ .reg .u64 t; cvta.to.shared.u64 t, %1; cvt.u32.u64 %0, t; }"
        : "=r"(a) : "l"(p));
    return a;
}
// hi = truncated top-16 bits, lo = rn-bf16 of exact residual.
__device__ __forceinline__ void split_pair(float2 v, uint32_t& hi, uint32_t& lo) {
    uint32_t ax = __float_as_uint(v.x), bx = __float_as_uint(v.y);
    hi = __byte_perm(ax, bx, 0x7632);
    float lx = v.x - __uint_as_float(ax & 0xFFFF0000u);
    float ly = v.y - __uint_as_float(bx & 0xFFFF0000u);
    asm("cvt.rn.bf16x2.f32 %0, %1, %2;" : "=r"(lo) : "f"(ly), "f"(lx));
}
__device__ __forceinline__ void ldsm_x4(uint32_t* r, uint32_t addr) {
    asm volatile("ldmatrix.sync.aligned.m8n8.x4.shared.b16 {%0,%1,%2,%3}, [%4];"
                 : "=r"(r[0]), "=r"(r[1]), "=r"(r[2]), "=r"(r[3]) : "r"(addr));
}
__device__ __forceinline__ void ldsm_x4_t(uint32_t* r, uint32_t addr) {
    asm volatile("ldmatrix.sync.aligned.m8n8.x4.trans.shared.b16 {%0,%1,%2,%3}, [%4];"
                 : "=r"(r[0]), "=r"(r[1]), "=r"(r[2]), "=r"(r[3]) : "r"(addr));
}
__device__ __forceinline__ void mma_bf16(float* c, const uint32_t* a,
                                         const uint32_t* b) {
    asm volatile(
        "mma.sync.aligned.m16n8k16.row.col.f32.bf16.bf16.f32 "
        "{%0,%1,%2,%3}, {%4,%5,%6,%7}, {%8,%9}, {%0,%1,%2,%3};"
        : "+f"(c[0]), "+f"(c[1]), "+f"(c[2]), "+f"(c[3])
        : "r"(a[0]), "r"(a[1]), "r"(a[2]), "r"(a[3]), "r"(b[0]), "r"(b[1]));
}
__device__ __forceinline__ void cp16(uint32_t s, const void* g) {
    asm volatile("cp.async.cg.shared.global [%0], [%1], 16;" :: "r"(s), "l"(g));
}
__device__ __forceinline__ void cp_commit() {
    asm volatile("cp.async.commit_group;");
}
template<int N> __device__ __forceinline__ void cp_wait() {
    asm volatile("cp.async.wait_group %0;" :: "n"(N));
}

// ---------------------------------------------------------------------------
// fp32 -> split bf16 planes (one-shot converts for x / W_qkv / W_out)
// ---------------------------------------------------------------------------
__global__ void split_kernel(const float4* __restrict__ src,
                             uint16_t* __restrict__ hi,
                             uint16_t* __restrict__ lo, int n4)
{
    int i = blockIdx.x * blockDim.x + threadIdx.x;
    if (i >= n4) return;
    float4 v = src[i];
    uint32_t h0, l0, h1, l1;
    split_pair(make_float2(v.x, v.y), h0, l0);
    split_pair(make_float2(v.z, v.w), h1, l1);
    ((uint2*)hi)[i] = make_uint2(h0, h1);
    ((uint2*)lo)[i] = make_uint2(l0, l1);
}

// ===========================================================================
// GEMM v4: pre-split bf16 inputs, 2-stage cp.async, 2 CTAs/SM,
// TERM-MAJOR HMMA ordering (dependency distance 8 per accumulator).
// 128x128 tile, K-chunk 32, 256 threads = 8 warps (4m x 2n).
// Per-accumulator add order unchanged (hh -> hl -> lh, same k order):
// results bit-identical to R10.
// ===========================================================================
#define G_OAH  0
#define G_OAL  10240
#define G_OBH  20480
#define G_OBL  29184
#define G_ST   37888
#define G_SMEM (2 * G_ST)   // 75776 -> 2 CTAs/SM

template<int WRITE_SPLIT>
__global__ __launch_bounds__(256, 2)
void gemm_tc2(const uint16_t* __restrict__ Ah, const uint16_t* __restrict__ Al,
              const uint16_t* __restrict__ Bh, const uint16_t* __restrict__ Bl,
              const float* __restrict__ bias,
              float* __restrict__ Cf,
              uint16_t* __restrict__ Ch, uint16_t* __restrict__ Cl,
              int N, int K, int qcols)
{
    extern __shared__ char sm[];
    const uint32_t sbase = smem_u32(sm);

    const int tid  = threadIdx.x;
    const int lane = tid & 31;
    const int wid  = tid >> 5;
    const int wm   = wid & 3;
    const int wn   = wid >> 2;
    const int row0 = blockIdx.y * 128;
    const int col0 = blockIdx.x * 128;

    const int ar  = tid >> 1;
    const int akc = (tid & 1) * 2;
    const int br  = tid >> 3;
    const int bnc = (tid & 7) * 2;

    const uint16_t* Aph = Ah + (size_t)(row0 + ar) * K + akc * 8;
    const uint16_t* Apl = Al + (size_t)(row0 + ar) * K + akc * 8;
    const uint16_t* Bph = Bh + (size_t)br * N + col0 + bnc * 8;
    const uint16_t* Bpl = Bl + (size_t)br * N + col0 + bnc * 8;

    const uint32_t sao0 = (uint32_t)(ar * 40 + akc * 8) * 2u;
    const uint32_t sao1 = sao0 + 16u;
    const uint32_t sbo0 = (uint32_t)(br * 136 + bnc * 8) * 2u;
    const uint32_t sbo1 = sbo0 + 16u;

    const int g  = lane >> 3;
    const int rr = lane & 7;
    uint32_t abase[2];
    #pragma unroll
    for (int mt = 0; mt < 2; mt++)
        abase[mt] = (uint32_t)((wm * 32 + mt * 16 + (g & 1) * 8 + rr) * 40
                               + (g >> 1) * 8) * 2u;
    uint32_t bbase[4];
    #pragma unroll
    for (int np = 0; np < 4; np++)
        bbase[np] = (uint32_t)(((g & 1) * 8 + rr) * 136
                               + wn * 64 + np * 16 + (g >> 1) * 8) * 2u;

    float acc[2][8][4];
    #pragma unroll
    for (int i = 0; i < 2; i++)
        #pragma unroll
        for (int j = 0; j < 8; j++)
            #pragma unroll
            for (int r = 0; r < 4; r++)
                acc[i][j][r] = 0.f;

    auto LOAD = [&](int st, int k0) {
        uint32_t s0 = sbase + st * G_ST;
        cp16(s0 + G_OAH + sao0, Aph + k0);
        cp16(s0 + G_OAH + sao1, Aph + k0 + 8);
        cp16(s0 + G_OAL + sao0, Apl + k0);
        cp16(s0 + G_OAL + sao1, Apl + k0 + 8);
        cp16(s0 + G_OBH + sbo0, Bph + (size_t)k0 * N);
        cp16(s0 + G_OBH + sbo1, Bph + (size_t)k0 * N + 8);
        cp16(s0 + G_OBL + sbo0, Bpl + (size_t)k0 * N);
        cp16(s0 + G_OBL + sbo1, Bpl + (size_t)k0 * N + 8);
    };

    const int nk = K / 32;
    LOAD(0, 0);  cp_commit();
    LOAD(1, 32); cp_commit();

    for (int kc = 0; kc < nk; kc++) {
        if (kc < nk - 1) cp_wait<1>();
        else             cp_wait<0>();
        __syncthreads();

        uint32_t s0 = sbase + (kc & 1) * G_ST;
        #pragma unroll
        for (int ks = 0; ks < 2; ks++) {
            const uint32_t ka = ks * 32u;     // 16 elems * 2B
            const uint32_t kb = ks * 4352u;   // 16 rows * 272B
            uint32_t ahi[2][4], alo[2][4];
            ldsm_x4(ahi[0], s0 + G_OAH + abase[0] + ka);
            ldsm_x4(ahi[1], s0 + G_OAH + abase[1] + ka);
            ldsm_x4(alo[0], s0 + G_OAL + abase[0] + ka);
            ldsm_x4(alo[1], s0 + G_OAL + abase[1] + ka);
            #pragma unroll
            for (int nph = 0; nph < 2; nph++) {
                uint32_t bh[2][4], bl[2][4];
                ldsm_x4_t(bh[0], s0 + G_OBH + bbase[2 * nph + 0] + kb);
                ldsm_x4_t(bl[0], s0 + G_OBL + bbase[2 * nph + 0] + kb);
                ldsm_x4_t(bh[1], s0 + G_OBH + bbase[2 * nph + 1] + kb);
                ldsm_x4_t(bl[1], s0 + G_OBL + bbase[2 * nph + 1] + kb);
                // term 1: Ahi*Bhi over 8 distinct accumulators
                #pragma unroll
                for (int p = 0; p < 2; p++)
                    #pragma unroll
                    for (int mt = 0; mt < 2; mt++) {
                        mma_bf16(acc[mt][4 * nph + 2 * p + 0], ahi[mt], bh[p]);
                        mma_bf16(acc[mt][4 * nph + 2 * p + 1], ahi[mt], bh[p] + 2);
                    }
                // term 2: Ahi*Blo
                #pragma unroll
                for (int p = 0; p < 2; p++)
                    #pragma unroll
                    for (int mt = 0; mt < 2; mt++) {
                        mma_bf16(acc[mt][4 * nph + 2 * p + 0], ahi[mt], bl[p]);
                        mma_bf16(acc[mt][4 * nph + 2 * p + 1], ahi[mt], bl[p] + 2);
                    }
                // term 3: Alo*Bhi
                #pragma unroll
                for (int p = 0; p < 2; p++)
                    #pragma unroll
                    for (int mt = 0; mt < 2; mt++) {
                        mma_bf16(acc[mt][4 * nph + 2 * p + 0], alo[mt], bh[p]);
                        mma_bf16(acc[mt][4 * nph + 2 * p + 1], alo[mt], bh[p] + 2);
                    }
            }
        }
        __syncthreads();
        if (kc + 2 < nk) { LOAD(kc & 1, (kc + 2) * 32); cp_commit(); }
    }

    // ---- epilogue ----
    const int ml = lane >> 2;
    const int nl = 2 * (lane & 3);
    #pragma unroll
    for (int mt = 0; mt < 2; mt++) {
        #pragma unroll
        for (int nt = 0; nt < 8; nt++) {
            int m = row0 + wm * 32 + mt * 16 + ml;
            int n = col0 + wn * 64 + nt * 8 + nl;
            float2 bv = *(const float2*)&bias[n];
            float* c = acc[mt][nt];
            float v0 = c[0] + bv.x, v1 = c[1] + bv.y;
            float w0 = c[2] + bv.x, w1 = c[3] + bv.y;
            if (WRITE_SPLIT) {
                float sc = (n < qcols) ? 0.125f : 1.0f;
                v0 *= sc; v1 *= sc; w0 *= sc; w1 *= sc;
                uint32_t h, l;
                split_pair(make_float2(v0, v1), h, l);
                *(uint32_t*)(Ch + (size_t)m * N + n) = h;
                *(uint32_t*)(Cl + (size_t)m * N + n) = l;
                split_pair(make_float2(w0, w1), h, l);
                *(uint32_t*)(Ch + (size_t)(m + 8) * N + n) = h;
                *(uint32_t*)(Cl + (size_t)(m + 8) * N + n) = l;
            } else {
                *(float2*)(Cf + (size_t)m * N + n) = make_float2(v0, v1);
                *(float2*)(Cf + (size_t)(m + 8) * N + n) = make_float2(w0, w1);
            }
        }
    }
}

// ===========================================================================
// Flash attention v2: term-major HMMA ordering + cp.async double-buffered
// K/V stages. Block = 128 q-rows x one (b,h); 256 threads. K-tile 64.
// Per-accumulator add order identical to R10 (bit-identical results).
// ===========================================================================
#define FA_PAD  72
#define O_QHI   0
#define O_QLO   18432                       // 128*72*2
#define KV_ST0  36864
#define P_KHI   0
#define P_KLO   9216
#define P_VHI   18432
#define P_VLO   27648
#define KV_STG  36864                       // 4 planes * 64*72*2
#define FA_SMEM (KV_ST0 + 2 * KV_STG)       // 110592

__global__ __launch_bounds__(256)
void flash_attn_mma_kernel(const uint16_t* __restrict__ qkv_hi,
                           const uint16_t* __restrict__ qkv_lo,
                           uint16_t* __restrict__ attn_hi,
                           uint16_t* __restrict__ attn_lo)
{
    extern __shared__ char fsm[];
    const uint32_t sb = smem_u32(fsm);

    const int tid  = threadIdx.x;
    const int lane = tid & 31;
    const int wm   = tid >> 5;
    const int qt   = blockIdx.x;
    const int b    = blockIdx.y >> 4;
    const int h    = blockIdx.y & 15;

    // ---- load Q tile from planes (already scaled by 1/8) ----
    {
        const int r  = tid >> 1;
        const int c0 = (tid & 1) * 32;
        const uint16_t* qh = qkv_hi + (size_t)(b * SEQ + qt * 128 + r) * QKVW
                                    + h * HD + c0;
        const uint16_t* ql = qkv_lo + (size_t)(b * SEQ + qt * 128 + r) * QKVW
                                    + h * HD + c0;
        uint32_t base = (uint32_t)(r * FA_PAD + c0) * 2u;
        #pragma unroll
        for (int s = 0; s < 4; s++) {
            *(uint4*)(fsm + O_QHI + base + 16 * s) = *(const uint4*)(qh + 8 * s);
            *(uint4*)(fsm + O_QLO + base + 16 * s) = *(const uint4*)(ql + 8 * s);
        }
    }

    // K/V cp.async loader mapping
    const int kr  = tid >> 2;           // 0..63
    const int kc0 = (tid & 3) * 16;     // elem offset
    auto LOADKV = [&](int kt, int st) {
        size_t roff = (size_t)(b * SEQ + kt * 64 + kr) * QKVW + h * HD + kc0;
        const uint16_t* gh = qkv_hi + roff;
        const uint16_t* gl = qkv_lo + roff;
        uint32_t d = sb + KV_ST0 + (uint32_t)(st * KV_STG)
                   + (uint32_t)(kr * FA_PAD + kc0) * 2u;
        cp16(d + P_KHI,      gh + EMB);
        cp16(d + P_KHI + 16, gh + EMB + 8);
        cp16(d + P_KLO,      gl + EMB);
        cp16(d + P_KLO + 16, gl + EMB + 8);
        cp16(d + P_VHI,      gh + 2 * EMB);
        cp16(d + P_VHI + 16, gh + 2 * EMB + 8);
        cp16(d + P_VLO,      gl + 2 * EMB);
        cp16(d + P_VLO + 16, gl + 2 * EMB + 8);
    };

    LOADKV(0, 0);
    cp_commit();
    __syncthreads();   // Q tile visible

    // ---- preload Q fragments (held in registers) ----
    const int g  = lane >> 3;
    const int rr = lane & 7;
    uint32_t qhi[4][4], qlo[4][4];
    {
        uint32_t moff = (uint32_t)((wm * 16 + (g & 1) * 8 + rr) * FA_PAD) * 2u;
        #pragma unroll
        for (int t = 0; t < 4; t++) {
            uint32_t koff = (uint32_t)((g >> 1) * 8 + 16 * t) * 2u;
            ldsm_x4(qhi[t], sb + O_QHI + moff + koff);
            ldsm_x4(qlo[t], sb + O_QLO + moff + koff);
        }
    }

    const uint32_t kbase = (uint32_t)(((g >> 1) * 8 + rr) * FA_PAD + (g & 1) * 8) * 2u;
    const uint32_t vbase = (uint32_t)(((g & 1) * 8 + rr) * FA_PAD + (g >> 1) * 8) * 2u;

    float m0 = -1e30f, m1 = -1e30f, l0 = 0.f, l1 = 0.f;
    float o[8][4];
    #pragma unroll
    for (int j = 0; j < 8; j++)
        #pragma unroll
        for (int r = 0; r < 4; r++) o[j][r] = 0.f;

    for (int kt = 0; kt < SEQ / 64; kt++) {
        cp_wait<0>();
        __syncthreads();   // K/V stage ready; prev compute done
        if (kt + 1 < SEQ / 64) { LOADKV(kt + 1, (kt + 1) & 1); cp_commit(); }

        const uint32_t stg = sb + KV_ST0 + (uint32_t)((kt & 1) * KV_STG);

        // ---- S = Q K^T : term-major, 8-acc dependency distance ----
        float s[8][4];
        #pragma unroll
        for (int j = 0; j < 8; j++)
            #pragma unroll
            for (int r4 = 0; r4 < 4; r4++) s[j][r4] = 0.f;

        #pragma unroll
        for (int t = 0; t < 4; t++) {
            uint32_t kfh[4][4], kfl[4][4];
            #pragma unroll
            for (int nt = 0; nt < 4; nt++) {
                uint32_t off = kbase + (uint32_t)(nt * 16 * FA_PAD + 16 * t) * 2u;
                ldsm_x4(kfh[nt], stg + P_KHI + off);
                ldsm_x4(kfl[nt], stg + P_KLO + off);
            }
            #pragma unroll
            for (int nt = 0; nt < 4; nt++) {
                mma_bf16(s[2 * nt + 0], qhi[t], kfh[nt]);
                mma_bf16(s[2 * nt + 1], qhi[t], kfh[nt] + 2);
            }
            #pragma unroll
            for (int nt = 0; nt < 4; nt++) {
                mma_bf16(s[2 * nt + 0], qhi[t], kfl[nt]);
                mma_bf16(s[2 * nt + 1], qhi[t], kfl[nt] + 2);
            }
            #pragma unroll
            for (int nt = 0; nt < 4; nt++) {
                mma_bf16(s[2 * nt + 0], qlo[t], kfh[nt]);
                mma_bf16(s[2 * nt + 1], qlo[t], kfh[nt] + 2);
            }
        }

        // ---- online softmax ----
        float mx0 = -1e30f, mx1 = -1e30f;
        #pragma unroll
        for (int j = 0; j < 8; j++) {
            mx0 = fmaxf(mx0, fmaxf(s[j][0], s[j][1]));
            mx1 = fmaxf(mx1, fmaxf(s[j][2], s[j][3]));
        }
        mx0 = fmaxf(mx0, __shfl_xor_sync(0xffffffffu, mx0, 1));
        mx0 = fmaxf(mx0, __shfl_xor_sync(0xffffffffu, mx0, 2));
        mx1 = fmaxf(mx1, __shfl_xor_sync(0xffffffffu, mx1, 1));
        mx1 = fmaxf(mx1, __shfl_xor_sync(0xffffffffu, mx1, 2));

        float mn0 = fmaxf(m0, mx0), mn1 = fmaxf(m1, mx1);
        float a0 = __expf(m0 - mn0), a1 = __expf(m1 - mn1);
        m0 = mn0; m1 = mn1;

        float sum0 = 0.f, sum1 = 0.f;
        #pragma unroll
        for (int j = 0; j < 8; j++) {
            s[j][0] = __expf(s[j][0] - mn0);
            s[j][1] = __expf(s[j][1] - mn0);
            s[j][2] = __expf(s[j][2] - mn1);
            s[j][3] = __expf(s[j][3] - mn1);
            sum0 += s[j][0] + s[j][1];
            sum1 += s[j][2] + s[j][3];
        }
        sum0 += __shfl_xor_sync(0xffffffffu, sum0, 1);
        sum0 += __shfl_xor_sync(0xffffffffu, sum0, 2);
        sum1 += __shfl_xor_sync(0xffffffffu, sum1, 1);
        sum1 += __shfl_xor_sync(0xffffffffu, sum1, 2);
        l0 = l0 * a0 + sum0;
        l1 = l1 * a1 + sum1;

        #pragma unroll
        for (int j = 0; j < 8; j++) {
            o[j][0] *= a0; o[j][1] *= a0;
            o[j][2] *= a1; o[j][3] *= a1;
        }

        // ---- o += P V : term-major, 8-acc dependency distance ----
        #pragma unroll
        for (int t = 0; t < 4; t++) {
            uint32_t phi[4], plo[4];
            split_pair(make_float2(s[2*t][0],   s[2*t][1]),   phi[0], plo[0]);
            split_pair(make_float2(s[2*t][2],   s[2*t][3]),   phi[1], plo[1]);
            split_pair(make_float2(s[2*t+1][0], s[2*t+1][1]), phi[2], plo[2]);
            split_pair(make_float2(s[2*t+1][2], s[2*t+1][3]), phi[3], plo[3]);
            uint32_t vfh[4][4], vfl[4][4];
            #pragma unroll
            for (int nt = 0; nt < 4; nt++) {
                uint32_t off = vbase + (uint32_t)(t * 16 * FA_PAD + nt * 16) * 2u;
                ldsm_x4_t(vfh[nt], stg + P_VHI + off);
                ldsm_x4_t(vfl[nt], stg + P_VLO + off);
            }
            #pragma unroll
            for (int nt = 0; nt < 4; nt++) {
                mma_bf16(o[2 * nt + 0], phi, vfh[nt]);
                mma_bf16(o[2 * nt + 1], phi, vfh[nt] + 2);
            }
            #pragma unroll
            for (int nt = 0; nt < 4; nt++) {
                mma_bf16(o[2 * nt + 0], phi, vfl[nt]);
                mma_bf16(o[2 * nt + 1], phi, vfl[nt] + 2);
            }
            #pragma unroll
            for (int nt = 0; nt < 4; nt++) {
                mma_bf16(o[2 * nt + 0], plo, vfh[nt]);
                mma_bf16(o[2 * nt + 1], plo, vfh[nt] + 2);
            }
        }
    }

    // ---- epilogue: normalize, split, write planes ----
    float inv0 = 1.f / l0, inv1 = 1.f / l1;
    int row = b * SEQ + qt * 128 + wm * 16 + (lane >> 2);
    size_t e0 = (size_t)row * EMB + h * HD + 2 * (lane & 3);
    #pragma unroll
    for (int j = 0; j < 8; j++) {
        uint32_t hh, ll;
        split_pair(make_float2(o[j][0] * inv0, o[j][1] * inv0), hh, ll);
        *(uint32_t*)(attn_hi + e0 + 8 * j) = hh;
        *(uint32_t*)(attn_lo + e0 + 8 * j) = ll;
        split_pair(make_float2(o[j][2] * inv1, o[j][3] * inv1), hh, ll);
        *(uint32_t*)(attn_hi + e0 + (size_t)8 * EMB + 8 * j) = hh;
        *(uint32_t*)(attn_lo + e0 + (size_t)8 * EMB + 8 * j) = ll;
    }
}

// ---------------------------------------------------------------------------
extern "C" void kernel_launch(void* const* d_in, const int* in_sizes, int n_in,
                              void* d_out, int out_size)
{
    (void)in_sizes; (void)n_in; (void)out_size;
    const float* x     = (const float*)d_in[0];
    const float* w_qkv = (const float*)d_in[1];
    const float* b_qkv = (const float*)d_in[2];
    const float* w_out = (const float*)d_in[3];
    const float* b_out = (const float*)d_in[4];
    float* out = (float*)d_out;

    uint16_t *x_hi, *x_lo, *wq_hi, *wq_lo, *wo_hi, *wo_lo;
    uint16_t *qkv_hi, *qkv_lo, *attn_hi, *attn_lo;
    cudaGetSymbolAddress((void**)&x_hi,   g_x_hi);
    cudaGetSymbolAddress((void**)&x_lo,   g_x_lo);
    cudaGetSymbolAddress((void**)&wq_hi,  g_wqkv_hi);
    cudaGetSymbolAddress((void**)&wq_lo,  g_wqkv_lo);
    cudaGetSymbolAddress((void**)&wo_hi,  g_wout_hi);
    cudaGetSymbolAddress((void**)&wo_lo,  g_wout_lo);
    cudaGetSymbolAddress((void**)&qkv_hi, g_qkv_hi);
    cudaGetSymbolAddress((void**)&qkv_lo, g_qkv_lo);
    cudaGetSymbolAddress((void**)&attn_hi, g_attn_hi);
    cudaGetSymbolAddress((void**)&attn_lo, g_attn_lo);

    cudaFuncSetAttribute(gemm_tc2<1>,
                         cudaFuncAttributeMaxDynamicSharedMemorySize, G_SMEM);
    cudaFuncSetAttribute(gemm_tc2<0>,
                         cudaFuncAttributeMaxDynamicSharedMemorySize, G_SMEM);
    cudaFuncSetAttribute(flash_attn_mma_kernel,
                         cudaFuncAttributeMaxDynamicSharedMemorySize, FA_SMEM);

    // 0) one-shot splits of inputs
    split_kernel<<<(NROWS * EMB / 4) / 256, 256>>>(
        (const float4*)x, x_hi, x_lo, NROWS * EMB / 4);
    split_kernel<<<(EMB * QKVW / 4) / 256, 256>>>(
        (const float4*)w_qkv, wq_hi, wq_lo, EMB * QKVW / 4);
    split_kernel<<<(EMB * EMB / 4) / 256, 256>>>(
        (const float4*)w_out, wo_hi, wo_lo, EMB * EMB / 4);

    // 1) QKV projection -> split planes (Q cols pre-scaled by 1/8)
    gemm_tc2<1><<<dim3(QKVW / 128, NROWS / 128), 256, G_SMEM>>>(
        x_hi, x_lo, wq_hi, wq_lo, b_qkv, nullptr, qkv_hi, qkv_lo,
        QKVW, EMB, EMB);

    // 2) attention -> split planes
    flash_attn_mma_kernel<<<dim3(SEQ / 128, BATCH * HEADS), 256, FA_SMEM>>>(
        qkv_hi, qkv_lo, attn_hi, attn_lo);

    // 3) output projection -> fp32 out
    gemm_tc2<0><<<dim3(EMB / 128, NROWS / 128), 256, G_SMEM>>>(
        attn_hi, attn_lo, wo_hi, wo_lo, b_out, out, nullptr, nullptr,
        EMB, EMB, 0);
}